// round 4
// baseline (speedup 1.0000x reference)
#include <cuda_runtime.h>

#define NN 100000
#define EE 1600000
#define TOTE 1700000
#define D 128
#define ZA 0.8f
#define ZB 0.2f
#define NEG 0.2f

// ---------------- scratch (device globals; no runtime allocation) ----------------
__device__ __align__(256) float  g_x [NN * D];    // mixed transformed features
__device__ __align__(256) float  g_xp[NN * D];    // GAT-projected features
__device__ __align__(256) float  g_acc[NN * D];   // GAT aggregation accumulator
__device__ __align__(256) float  g_asrc[NN];
__device__ __align__(256) float  g_adst[NN];
__device__ __align__(256) float  g_ex[TOTE];
__device__ __align__(256) float  g_denom[NN];
__device__ __align__(256) int    g_src[TOTE];
__device__ __align__(256) int    g_dst[TOTE];
__device__ __align__(256) unsigned char g_mask[NN];
__device__ __align__(256) double g_cs[D];
__device__ __align__(256) double g_cq[D];
__device__ __align__(256) float  g_A[D];          // norm scale per feature
__device__ __align__(256) float  g_B[D];          // norm shift per feature (incl. gat_bias)
__device__ __align__(256) float  g_Wa[D * 2 * D]; // combined+scaled weights (mask=true)
__device__ __align__(256) float  g_Wb[D * 2 * D]; // combined+scaled weights (mask=false)
__device__ __align__(256) float  g_ba[D];
__device__ __align__(256) float  g_bb[D];
__device__ __align__(256) int    g_listT[NN];
__device__ __align__(256) int    g_listF[NN];
__device__            int        g_cnt[2];
__device__            int        g_flags[2];      // [0]=edge is int64, [1]=mask kind 0=byte/1=int32/2=float32

// ---------------- dtype detection (harness may pass int64 as int32, bool as anything) ----------------
// Edge probe reads 512 bytes (buffer >= 12.8MB for either dtype). Mask probe reads
// 1024 bytes (buffer >= 100000 bytes for any candidate dtype). Both provably in-bounds.
__global__ void k_detect(const void* ei, const void* mask) {
    if (threadIdx.x != 0 || blockIdx.x != 0) return;
    // Edge index: int64 LE with values in [0, 1e5) => every odd int32 word is 0.
    // Native int32: P(64 random node ids all zero) ~ 0.
    const int* e32 = (const int*)ei;
    int allz = 1;
    for (int i = 1; i < 128; i += 2) if (e32[i] != 0) { allz = 0; break; }
    g_flags[0] = allz;
    // Mask: probe 256 u32 words. int32 bools => all words in {0,1};
    // float32 bools => {0, 0x3F800000}; packed bytes => mixed-byte words almost surely.
    const unsigned int* m32 = (const unsigned int*)mask;
    int int_like = 1, float_like = 1;
    for (int i = 0; i < 256; i++) {
        unsigned int w = m32[i];
        if (!(w == 0u || w == 1u)) int_like = 0;
        if (!(w == 0u || w == 0x3F800000u)) float_like = 0;
    }
    g_flags[1] = int_like ? 1 : (float_like ? 2 : 0);
}

// ---------------- normalize inputs: indices -> int32 (+ self loops), mask -> uint8 ----------------
__global__ __launch_bounds__(256) void k_convert(const void* ei, const void* maskp) {
    int i = blockIdx.x * 256 + threadIdx.x;
    int e64 = g_flags[0], mk = g_flags[1];
    if (i < TOTE) {
        int s, d;
        if (i < EE) {
            if (e64) {
                const long long* e = (const long long*)ei;
                s = (int)e[i]; d = (int)e[EE + i];
            } else {
                const int* e = (const int*)ei;
                s = e[i]; d = e[EE + i];
            }
        } else { s = d = i - EE; }
        g_src[i] = s; g_dst[i] = d;
    }
    if (i < NN) {
        unsigned char m;
        if (mk == 0)      m = ((const unsigned char*)maskp)[i] != 0;
        else if (mk == 1) m = ((const int*)maskp)[i] != 0;
        else              m = ((const float*)maskp)[i] != 0.f;
        g_mask[i] = m;
    }
}

// ---------------- init ----------------
__global__ __launch_bounds__(256) void k_init() {
    size_t i = (size_t)blockIdx.x * blockDim.x + threadIdx.x;
    size_t stride = (size_t)gridDim.x * blockDim.x;
    for (size_t j = i; j < (size_t)NN * D; j += stride) g_acc[j] = 0.f;
    for (size_t j = i; j < NN; j += stride) g_denom[j] = 0.f;
    if (i < D) { g_cs[i] = 0.0; g_cq[i] = 0.0; }
    if (i == 0) { g_cnt[0] = 0; g_cnt[1] = 0; }
}

// ---------------- mask compaction ----------------
__global__ __launch_bounds__(256) void k_compact() {
    int i = blockIdx.x * blockDim.x + threadIdx.x;
    if (i < NN) {
        if (g_mask[i]) g_listT[atomicAdd(&g_cnt[0], 1)] = i;
        else           g_listF[atomicAdd(&g_cnt[1], 1)] = i;
    }
}

// ---------------- stage 1: x = mix(relu(x@W1^T+b1), relu(x@W0^T+b0), mask) ----------------
__global__ __launch_bounds__(256) void k_transform(
    const float* __restrict__ x, const float* __restrict__ W0, const float* __restrict__ b0,
    const float* __restrict__ W1, const float* __restrict__ b1)
{
    __shared__ __align__(16) float sA[64 * 16];
    __shared__ __align__(16) float sW0[16 * 132];
    __shared__ __align__(16) float sW1[16 * 132];
    int tid = threadIdx.x;
    int base = blockIdx.x * 64;
    int warp = tid >> 5, lane = tid & 31;
    int arow = tid >> 2, akq = tid & 3;

    float acc0[8][4], acc1[8][4];
#pragma unroll
    for (int r = 0; r < 8; r++)
#pragma unroll
        for (int i = 0; i < 4; i++) { acc0[r][i] = 0.f; acc1[r][i] = 0.f; }

    for (int kc = 0; kc < 8; kc++) {
        int grow = base + arow;
        float4 av = make_float4(0.f, 0.f, 0.f, 0.f);
        if (grow < NN) av = *(const float4*)&x[(size_t)grow * D + kc * 16 + akq * 4];
        *(float4*)&sA[arow * 16 + akq * 4] = av;
#pragma unroll
        for (int t = 0; t < 2; t++) {
            int idx = tid + t * 256;
            int j = idx >> 2, kq = idx & 3;
            float4 w0 = *(const float4*)&W0[j * D + kc * 16 + kq * 4];
            float4 w1 = *(const float4*)&W1[j * D + kc * 16 + kq * 4];
            sW0[(kq * 4 + 0) * 132 + j] = w0.x; sW0[(kq * 4 + 1) * 132 + j] = w0.y;
            sW0[(kq * 4 + 2) * 132 + j] = w0.z; sW0[(kq * 4 + 3) * 132 + j] = w0.w;
            sW1[(kq * 4 + 0) * 132 + j] = w1.x; sW1[(kq * 4 + 1) * 132 + j] = w1.y;
            sW1[(kq * 4 + 2) * 132 + j] = w1.z; sW1[(kq * 4 + 3) * 132 + j] = w1.w;
        }
        __syncthreads();
#pragma unroll
        for (int kk = 0; kk < 16; kk++) {
            float4 w0 = *(const float4*)&sW0[kk * 132 + lane * 4];
            float4 w1 = *(const float4*)&sW1[kk * 132 + lane * 4];
#pragma unroll
            for (int r = 0; r < 8; r++) {
                float a = sA[(warp * 8 + r) * 16 + kk];
                acc0[r][0] += a * w0.x; acc0[r][1] += a * w0.y;
                acc0[r][2] += a * w0.z; acc0[r][3] += a * w0.w;
                acc1[r][0] += a * w1.x; acc1[r][1] += a * w1.y;
                acc1[r][2] += a * w1.z; acc1[r][3] += a * w1.w;
            }
        }
        __syncthreads();
    }
    float bb0[4], bb1[4];
#pragma unroll
    for (int i = 0; i < 4; i++) { bb0[i] = b0[lane * 4 + i]; bb1[i] = b1[lane * 4 + i]; }
#pragma unroll
    for (int r = 0; r < 8; r++) {
        int grow = base + warp * 8 + r;
        if (grow < NN) {
            bool m = g_mask[grow] != 0;
            float res[4];
#pragma unroll
            for (int i = 0; i < 4; i++) {
                float v0 = fmaxf(acc0[r][i] + bb0[i], 0.f);
                float v1 = fmaxf(acc1[r][i] + bb1[i], 0.f);
                res[i] = m ? (ZA * v1 + ZB * v0) : (ZA * v0 + ZB * v1);
            }
            *(float4*)&g_x[(size_t)grow * D + lane * 4] = make_float4(res[0], res[1], res[2], res[3]);
        }
    }
}

// ---------------- GAT projection: xp = x@gatW^T ; a_src=xp.att_src ; a_dst=xp.att_dst ----------------
__global__ __launch_bounds__(256) void k_gat(
    const float* __restrict__ W, const float* __restrict__ att_s, const float* __restrict__ att_d)
{
    __shared__ __align__(16) float sA[64 * 16];
    __shared__ __align__(16) float sW[16 * 132];
    int tid = threadIdx.x;
    int base = blockIdx.x * 64;
    int warp = tid >> 5, lane = tid & 31;
    int arow = tid >> 2, akq = tid & 3;

    float acc[8][4];
#pragma unroll
    for (int r = 0; r < 8; r++)
#pragma unroll
        for (int i = 0; i < 4; i++) acc[r][i] = 0.f;

    for (int kc = 0; kc < 8; kc++) {
        int grow = base + arow;
        float4 av = make_float4(0.f, 0.f, 0.f, 0.f);
        if (grow < NN) av = *(const float4*)&g_x[(size_t)grow * D + kc * 16 + akq * 4];
        *(float4*)&sA[arow * 16 + akq * 4] = av;
#pragma unroll
        for (int t = 0; t < 2; t++) {
            int idx = tid + t * 256;
            int j = idx >> 2, kq = idx & 3;
            float4 w = *(const float4*)&W[j * D + kc * 16 + kq * 4];
            sW[(kq * 4 + 0) * 132 + j] = w.x; sW[(kq * 4 + 1) * 132 + j] = w.y;
            sW[(kq * 4 + 2) * 132 + j] = w.z; sW[(kq * 4 + 3) * 132 + j] = w.w;
        }
        __syncthreads();
#pragma unroll
        for (int kk = 0; kk < 16; kk++) {
            float4 w = *(const float4*)&sW[kk * 132 + lane * 4];
#pragma unroll
            for (int r = 0; r < 8; r++) {
                float a = sA[(warp * 8 + r) * 16 + kk];
                acc[r][0] += a * w.x; acc[r][1] += a * w.y;
                acc[r][2] += a * w.z; acc[r][3] += a * w.w;
            }
        }
        __syncthreads();
    }
    float4 as4 = *(const float4*)&att_s[lane * 4];
    float4 ad4 = *(const float4*)&att_d[lane * 4];
#pragma unroll
    for (int r = 0; r < 8; r++) {
        int grow = base + warp * 8 + r;
        if (grow < NN)
            *(float4*)&g_xp[(size_t)grow * D + lane * 4] =
                make_float4(acc[r][0], acc[r][1], acc[r][2], acc[r][3]);
        float ps = acc[r][0] * as4.x + acc[r][1] * as4.y + acc[r][2] * as4.z + acc[r][3] * as4.w;
        float pd = acc[r][0] * ad4.x + acc[r][1] * ad4.y + acc[r][2] * ad4.z + acc[r][3] * ad4.w;
#pragma unroll
        for (int off = 16; off > 0; off >>= 1) {
            ps += __shfl_xor_sync(0xFFFFFFFFu, ps, off);
            pd += __shfl_xor_sync(0xFFFFFFFFu, pd, off);
        }
        if (lane == 0 && grow < NN) { g_asrc[grow] = ps; g_adst[grow] = pd; }
    }
}

// ---------------- edge pass 1: ex = exp(leaky_relu(a_src[s]+a_dst[d])) ; denom[d] += ex ----------------
// (shift-invariant softmax: max subtraction dropped; self-loops keep denom > 0)
__global__ __launch_bounds__(256) void k_edge1() {
    int e = blockIdx.x * blockDim.x + threadIdx.x;
    if (e >= TOTE) return;
    int s = g_src[e], dd = g_dst[e];
    if ((unsigned)s >= NN || (unsigned)dd >= NN) return;   // safety: degrade, don't crash
    float al = g_asrc[s] + g_adst[dd];
    al = al > 0.f ? al : NEG * al;
    float ex = expf(al);
    g_ex[e] = ex;
    atomicAdd(&g_denom[dd], ex);
}

// ---------------- edge pass 2: acc[d] += xp[s] * (ex/denom[d]) ; warp per edge, red.v4 ----------------
__global__ __launch_bounds__(256) void k_scatter() {
    int lane = threadIdx.x & 31;
    int e = blockIdx.x * 8 + (threadIdx.x >> 5);
    if (e >= TOTE) return;
    int s = g_src[e], dd = g_dst[e];
    if ((unsigned)s >= NN || (unsigned)dd >= NN) return;   // safety: degrade, don't crash
    float coef = g_ex[e] / (g_denom[dd] + 1e-16f);
    float4 v = *(const float4*)&g_xp[(size_t)s * D + lane * 4];
    float a = v.x * coef, b = v.y * coef, c = v.z * coef, d4 = v.w * coef;
    float* p = &g_acc[(size_t)dd * D + lane * 4];
    asm volatile("red.global.add.v4.f32 [%0], {%1, %2, %3, %4};"
                 :: "l"(p), "f"(a), "f"(b), "f"(c), "f"(d4) : "memory");
}

// ---------------- GraphNorm stats: per-feature sum / sumsq of (acc + gat_bias) ----------------
__global__ __launch_bounds__(128) void k_colstats(const float* __restrict__ gb) {
    int c = threadIdx.x;
    float b = gb[c];
    double s = 0.0, q = 0.0;
    for (int r = blockIdx.x; r < NN; r += gridDim.x) {
        float o = g_acc[(size_t)r * D + c] + b;
        s += o; q += (double)o * o;
    }
    atomicAdd(&g_cs[c], s);
    atomicAdd(&g_cq[c], q);
}

// ---------------- GraphNorm coefficients: norm(acc) = acc*A + B ----------------
__global__ void k_finalize(const float* __restrict__ gnw, const float* __restrict__ gnb,
                           const float* __restrict__ gms, const float* __restrict__ gatb) {
    int c = threadIdx.x;
    double m  = g_cs[c] / (double)NN;
    double e2 = g_cq[c] / (double)NN;
    double s  = (double)gms[c];
    double var = e2 - 2.0 * s * m * m + s * s * m * m;   // E[(o - s*m)^2]
    double A = (double)gnw[c] / sqrt(var + 1e-5);
    double B = (double)gnb[c] - s * m * A;
    g_A[c] = (float)A;
    g_B[c] = (float)((double)gatb[c] * A + B);           // gat_bias folded in
}

// ---------------- precompute mixed + norm-scaled final weights ----------------
__global__ __launch_bounds__(256) void k_prep(const float* __restrict__ Wc0, const float* __restrict__ bc0,
                                              const float* __restrict__ Wc1, const float* __restrict__ bc1) {
    __shared__ float2 rr[256];
    int j = blockIdx.x, c = threadIdx.x;
    float w0 = Wc0[j * 256 + c], w1 = Wc1[j * 256 + c];
    float wa = ZA * w1 + ZB * w0;
    float wb = ZA * w0 + ZB * w1;
    float pa = 0.f, pb = 0.f;
    if (c < D) {
        float B = g_B[c], A = g_A[c];
        pa = wa * B; pb = wb * B;
        wa *= A; wb *= A;
    }
    g_Wa[j * 256 + c] = wa;
    g_Wb[j * 256 + c] = wb;
    rr[c] = make_float2(pa, pb);
    __syncthreads();
    for (int off = 128; off > 0; off >>= 1) {
        if (c < off) { rr[c].x += rr[c + off].x; rr[c].y += rr[c + off].y; }
        __syncthreads();
    }
    if (c == 0) {
        g_ba[j] = ZA * bc1[j] + ZB * bc0[j] + rr[0].x;
        g_bb[j] = ZA * bc0[j] + ZB * bc1[j] + rr[0].y;
    }
}

// ---------------- final GEMM over compacted node lists: y = [acc, x_] @ Wsel^T + bsel ----------------
template <int WHICH>
__global__ __launch_bounds__(256) void k_final(const float* __restrict__ x_, float* __restrict__ out) {
    __shared__ int sIdx[64];
    __shared__ __align__(16) float sA[64 * 16];
    __shared__ __align__(16) float sW[16 * 132];
    int cnt = g_cnt[WHICH];
    int base = blockIdx.x * 64;
    if (base >= cnt) return;
    const int*   list = (WHICH == 0) ? g_listT : g_listF;
    const float* W    = (WHICH == 0) ? g_Wa : g_Wb;
    const float* bias = (WHICH == 0) ? g_ba : g_bb;
    int tid = threadIdx.x;
    int warp = tid >> 5, lane = tid & 31;
    int arow = tid >> 2, akq = tid & 3;
    if (tid < 64) sIdx[tid] = (base + tid < cnt) ? list[base + tid] : -1;
    __syncthreads();
    int aidx = sIdx[arow];

    float acc[8][4];
#pragma unroll
    for (int r = 0; r < 8; r++)
#pragma unroll
        for (int i = 0; i < 4; i++) acc[r][i] = 0.f;

    for (int kc = 0; kc < 16; kc++) {
        float4 av = make_float4(0.f, 0.f, 0.f, 0.f);
        if (aidx >= 0) {
            int k0 = kc * 16 + akq * 4;
            const float* srcp = (k0 < D) ? &g_acc[(size_t)aidx * D + k0]
                                         : &x_[(size_t)aidx * D + (k0 - D)];
            av = *(const float4*)srcp;
        }
        *(float4*)&sA[arow * 16 + akq * 4] = av;
#pragma unroll
        for (int t = 0; t < 2; t++) {
            int idx = tid + t * 256;
            int j = idx >> 2, kq = idx & 3;
            float4 w = *(const float4*)&W[j * 256 + kc * 16 + kq * 4];
            sW[(kq * 4 + 0) * 132 + j] = w.x; sW[(kq * 4 + 1) * 132 + j] = w.y;
            sW[(kq * 4 + 2) * 132 + j] = w.z; sW[(kq * 4 + 3) * 132 + j] = w.w;
        }
        __syncthreads();
#pragma unroll
        for (int kk = 0; kk < 16; kk++) {
            float4 w = *(const float4*)&sW[kk * 132 + lane * 4];
#pragma unroll
            for (int r = 0; r < 8; r++) {
                float a = sA[(warp * 8 + r) * 16 + kk];
                acc[r][0] += a * w.x; acc[r][1] += a * w.y;
                acc[r][2] += a * w.z; acc[r][3] += a * w.w;
            }
        }
        __syncthreads();
    }
    float4 bv = *(const float4*)&bias[lane * 4];
#pragma unroll
    for (int r = 0; r < 8; r++) {
        int idx2 = sIdx[warp * 8 + r];
        if (idx2 >= 0) {
            *(float4*)&out[(size_t)idx2 * D + lane * 4] =
                make_float4(acc[r][0] + bv.x, acc[r][1] + bv.y,
                            acc[r][2] + bv.z, acc[r][3] + bv.w);
        }
    }
}

// ---------------- launch ----------------
extern "C" void kernel_launch(void* const* d_in, const int* in_sizes, int n_in,
                              void* d_out, int out_size) {
    const float* x_      = (const float*)d_in[0];
    // d_in[1] = edge_attr (unused by reference)
    const float* W_t0    = (const float*)d_in[2];
    const float* b_t0    = (const float*)d_in[3];
    const float* W_t1    = (const float*)d_in[4];
    const float* b_t1    = (const float*)d_in[5];
    const float* gat_W   = (const float*)d_in[6];
    const float* att_src = (const float*)d_in[7];
    const float* att_dst = (const float*)d_in[8];
    const float* gat_b   = (const float*)d_in[9];
    const float* gn_w    = (const float*)d_in[10];
    const float* gn_b    = (const float*)d_in[11];
    const float* gn_ms   = (const float*)d_in[12];
    const float* W_c0    = (const float*)d_in[13];
    const float* b_c0    = (const float*)d_in[14];
    const float* W_c1    = (const float*)d_in[15];
    const float* b_c1    = (const float*)d_in[16];
    const void*  ei      = d_in[17];
    const void*  mask    = d_in[18];
    float* out = (float*)d_out;

    int gb = (NN + 63) / 64;

    k_detect<<<1, 32>>>(ei, mask);
    k_convert<<<(TOTE + 255) / 256, 256>>>(ei, mask);
    k_init<<<2048, 256>>>();
    k_compact<<<(NN + 255) / 256, 256>>>();
    k_transform<<<gb, 256>>>(x_, W_t0, b_t0, W_t1, b_t1);
    k_gat<<<gb, 256>>>(gat_W, att_src, att_dst);
    k_edge1<<<(TOTE + 255) / 256, 256>>>();
    k_scatter<<<(TOTE + 7) / 8, 256>>>();
    k_colstats<<<512, 128>>>(gat_b);
    k_finalize<<<1, 128>>>(gn_w, gn_b, gn_ms, gat_b);
    k_prep<<<128, 256>>>(W_c0, b_c0, W_c1, b_c1);
    k_final<0><<<gb, 256>>>(x_, out);
    k_final<1><<<gb, 256>>>(x_, out);
}

// round 5
// speedup vs baseline: 1.0578x; 1.0578x over previous
#include <cuda_runtime.h>

#define NN 100000
#define EE 1600000
#define TOTE 1700000
#define D 128
#define ZA 0.8f
#define ZB 0.2f
#define NEG 0.2f

// ---------------- scratch (device globals; no runtime allocation) ----------------
__device__ __align__(256) float  g_xp[NN * D];    // GAT-projected features
__device__ __align__(256) float  g_acc[NN * D];   // unnormalized GAT aggregation
__device__ __align__(256) float  g_asrc[NN];
__device__ __align__(256) float  g_adst[NN];
__device__ __align__(256) float  g_denom[NN];
__device__ __align__(256) float  g_invden[NN];
__device__ __align__(256) int    g_src[TOTE];
__device__ __align__(256) int    g_dst[TOTE];
__device__ __align__(256) unsigned char g_mask[NN];
__device__ __align__(256) double g_cs[D];
__device__ __align__(256) double g_cq[D];
__device__ __align__(256) float  g_A[D];          // norm scale per feature
__device__ __align__(256) float  g_B[D];          // norm shift per feature (incl. gat_bias)
__device__ __align__(256) float  g_Wa[D * 2 * D]; // combined+scaled weights (mask=true)
__device__ __align__(256) float  g_Wb[D * 2 * D]; // combined+scaled weights (mask=false)
__device__ __align__(256) float  g_ba[D];
__device__ __align__(256) float  g_bb[D];
__device__ __align__(256) int    g_listT[NN];
__device__ __align__(256) int    g_listF[NN];
__device__            int        g_cnt[2];
__device__            int        g_flags[2];      // [0]=edge is int64, [1]=mask kind

// ---------------- dtype detection ----------------
__global__ void k_detect(const void* ei, const void* mask) {
    if (threadIdx.x != 0 || blockIdx.x != 0) return;
    const int* e32 = (const int*)ei;
    int allz = 1;
    for (int i = 1; i < 128; i += 2) if (e32[i] != 0) { allz = 0; break; }
    g_flags[0] = allz;
    const unsigned int* m32 = (const unsigned int*)mask;
    int int_like = 1, float_like = 1;
    for (int i = 0; i < 256; i++) {
        unsigned int w = m32[i];
        if (!(w == 0u || w == 1u)) int_like = 0;
        if (!(w == 0u || w == 0x3F800000u)) float_like = 0;
    }
    g_flags[1] = int_like ? 1 : (float_like ? 2 : 0);
}

// ---------------- normalize inputs ----------------
__global__ __launch_bounds__(256) void k_convert(const void* ei, const void* maskp) {
    int i = blockIdx.x * 256 + threadIdx.x;
    int e64 = g_flags[0], mk = g_flags[1];
    if (i < TOTE) {
        int s, d;
        if (i < EE) {
            if (e64) {
                const long long* e = (const long long*)ei;
                s = (int)e[i]; d = (int)e[EE + i];
            } else {
                const int* e = (const int*)ei;
                s = e[i]; d = e[EE + i];
            }
        } else { s = d = i - EE; }
        g_src[i] = s; g_dst[i] = d;
    }
    if (i < NN) {
        unsigned char m;
        if (mk == 0)      m = ((const unsigned char*)maskp)[i] != 0;
        else if (mk == 1) m = ((const int*)maskp)[i] != 0;
        else              m = ((const float*)maskp)[i] != 0.f;
        g_mask[i] = m;
    }
}

// ---------------- init ----------------
__global__ __launch_bounds__(256) void k_init() {
    size_t i = (size_t)blockIdx.x * blockDim.x + threadIdx.x;
    size_t stride = (size_t)gridDim.x * blockDim.x;
    for (size_t j = i; j < (size_t)NN * D; j += stride) g_acc[j] = 0.f;
    for (size_t j = i; j < NN; j += stride) g_denom[j] = 0.f;
    if (i < D) { g_cs[i] = 0.0; g_cq[i] = 0.0; }
    if (i == 0) { g_cnt[0] = 0; g_cnt[1] = 0; }
}

// ---------------- mask compaction ----------------
__global__ __launch_bounds__(256) void k_compact() {
    int i = blockIdx.x * blockDim.x + threadIdx.x;
    if (i < NN) {
        if (g_mask[i]) g_listT[atomicAdd(&g_cnt[0], 1)] = i;
        else           g_listF[atomicAdd(&g_cnt[1], 1)] = i;
    }
}

// ---------------- fused: mix(relu GEMMs) -> smem -> GAT projection + attention dots ----------------
// Stage 1: xmix = mix(relu(x@W1^T+b1), relu(x@W0^T+b0), mask)   [64x128 tile in smem]
// Stage 2: xp = xmix@GW^T ; a_src = xp.att_s ; a_dst = xp.att_d
__global__ __launch_bounds__(256) void k_tg(
    const float* __restrict__ x,  const float* __restrict__ W0, const float* __restrict__ b0,
    const float* __restrict__ W1, const float* __restrict__ b1,
    const float* __restrict__ GW, const float* __restrict__ att_s, const float* __restrict__ att_d)
{
    __shared__ __align__(16) float sX [64 * 128];  // 32 KB mixed-feature tile
    __shared__ __align__(16) float sA [64 * 8];
    __shared__ __align__(16) float sW0[8 * 132];
    __shared__ __align__(16) float sW1[8 * 132];
    int tid = threadIdx.x;
    int base = blockIdx.x * 64;
    int warp = tid >> 5, lane = tid & 31;

    float acc0[8][4], acc1[8][4];
#pragma unroll
    for (int r = 0; r < 8; r++)
#pragma unroll
        for (int i = 0; i < 4; i++) { acc0[r][i] = 0.f; acc1[r][i] = 0.f; }

    // ---- stage 1: dual GEMM (K-chunk 8) ----
    for (int kc = 0; kc < 16; kc++) {
        if (tid < 128) {
            int arow = tid >> 1, akq = tid & 1;
            int grow = base + arow;
            float4 av = make_float4(0.f, 0.f, 0.f, 0.f);
            if (grow < NN) av = *(const float4*)&x[(size_t)grow * D + kc * 8 + akq * 4];
            *(float4*)&sA[arow * 8 + akq * 4] = av;
        }
        {
            int j = tid >> 1, kq = tid & 1;
            float4 w0 = *(const float4*)&W0[j * D + kc * 8 + kq * 4];
            float4 w1 = *(const float4*)&W1[j * D + kc * 8 + kq * 4];
            sW0[(kq * 4 + 0) * 132 + j] = w0.x; sW0[(kq * 4 + 1) * 132 + j] = w0.y;
            sW0[(kq * 4 + 2) * 132 + j] = w0.z; sW0[(kq * 4 + 3) * 132 + j] = w0.w;
            sW1[(kq * 4 + 0) * 132 + j] = w1.x; sW1[(kq * 4 + 1) * 132 + j] = w1.y;
            sW1[(kq * 4 + 2) * 132 + j] = w1.z; sW1[(kq * 4 + 3) * 132 + j] = w1.w;
        }
        __syncthreads();
#pragma unroll
        for (int kk = 0; kk < 8; kk++) {
            float4 w0 = *(const float4*)&sW0[kk * 132 + lane * 4];
            float4 w1 = *(const float4*)&sW1[kk * 132 + lane * 4];
#pragma unroll
            for (int r = 0; r < 8; r++) {
                float a = sA[(warp * 8 + r) * 8 + kk];
                acc0[r][0] += a * w0.x; acc0[r][1] += a * w0.y;
                acc0[r][2] += a * w0.z; acc0[r][3] += a * w0.w;
                acc1[r][0] += a * w1.x; acc1[r][1] += a * w1.y;
                acc1[r][2] += a * w1.z; acc1[r][3] += a * w1.w;
            }
        }
        __syncthreads();
    }
    // bias + relu + mix -> sX (written for all 64 rows; OOB rows only feed guarded writes later)
    {
        float bb0[4], bb1[4];
#pragma unroll
        for (int i = 0; i < 4; i++) { bb0[i] = b0[lane * 4 + i]; bb1[i] = b1[lane * 4 + i]; }
#pragma unroll
        for (int r = 0; r < 8; r++) {
            int grow = base + warp * 8 + r;
            bool m = (grow < NN) ? (g_mask[grow] != 0) : false;
            float res[4];
#pragma unroll
            for (int i = 0; i < 4; i++) {
                float v0 = fmaxf(acc0[r][i] + bb0[i], 0.f);
                float v1 = fmaxf(acc1[r][i] + bb1[i], 0.f);
                res[i] = m ? (ZA * v1 + ZB * v0) : (ZA * v0 + ZB * v1);
            }
            *(float4*)&sX[(warp * 8 + r) * 128 + lane * 4] =
                make_float4(res[0], res[1], res[2], res[3]);
        }
    }
    __syncthreads();

    // ---- stage 2: xp = sX @ GW^T ----
    float (&acc)[8][4] = acc0;  // reuse registers
#pragma unroll
    for (int r = 0; r < 8; r++)
#pragma unroll
        for (int i = 0; i < 4; i++) acc[r][i] = 0.f;

    for (int kc = 0; kc < 16; kc++) {
        {
            int j = tid >> 1, kq = tid & 1;
            float4 w = *(const float4*)&GW[j * D + kc * 8 + kq * 4];
            sW0[(kq * 4 + 0) * 132 + j] = w.x; sW0[(kq * 4 + 1) * 132 + j] = w.y;
            sW0[(kq * 4 + 2) * 132 + j] = w.z; sW0[(kq * 4 + 3) * 132 + j] = w.w;
        }
        __syncthreads();
#pragma unroll
        for (int kk = 0; kk < 8; kk++) {
            float4 w = *(const float4*)&sW0[kk * 132 + lane * 4];
#pragma unroll
            for (int r = 0; r < 8; r++) {
                float a = sX[(warp * 8 + r) * 128 + kc * 8 + kk];
                acc[r][0] += a * w.x; acc[r][1] += a * w.y;
                acc[r][2] += a * w.z; acc[r][3] += a * w.w;
            }
        }
        __syncthreads();
    }
    float4 as4 = *(const float4*)&att_s[lane * 4];
    float4 ad4 = *(const float4*)&att_d[lane * 4];
#pragma unroll
    for (int r = 0; r < 8; r++) {
        int grow = base + warp * 8 + r;
        if (grow < NN)
            *(float4*)&g_xp[(size_t)grow * D + lane * 4] =
                make_float4(acc[r][0], acc[r][1], acc[r][2], acc[r][3]);
        float ps = acc[r][0] * as4.x + acc[r][1] * as4.y + acc[r][2] * as4.z + acc[r][3] * as4.w;
        float pd = acc[r][0] * ad4.x + acc[r][1] * ad4.y + acc[r][2] * ad4.z + acc[r][3] * ad4.w;
#pragma unroll
        for (int off = 16; off > 0; off >>= 1) {
            ps += __shfl_xor_sync(0xFFFFFFFFu, ps, off);
            pd += __shfl_xor_sync(0xFFFFFFFFu, pd, off);
        }
        if (lane == 0 && grow < NN) { g_asrc[grow] = ps; g_adst[grow] = pd; }
    }
}

// ---------------- single-pass edge aggregation ----------------
// acc[d] += exp(leaky(a_src[s]+a_dst[d])) * xp[s] ; denom[d] += exp(...)
// (division by denom is outside the segment sum — mathematically identical;
//  softmax max-shift dropped: shift-invariant and self-loops keep denom > 0)
__global__ __launch_bounds__(256) void k_scatter() {
    int lane = threadIdx.x & 31;
    int e = blockIdx.x * 8 + (threadIdx.x >> 5);
    if (e >= TOTE) return;
    int s = g_src[e], dd = g_dst[e];
    if ((unsigned)s >= NN || (unsigned)dd >= NN) return;   // safety: degrade, don't crash
    float al = g_asrc[s] + g_adst[dd];
    al = al > 0.f ? al : NEG * al;
    float ex = expf(al);
    float4 v = *(const float4*)&g_xp[(size_t)s * D + lane * 4];
    float a = v.x * ex, b = v.y * ex, c = v.z * ex, d4 = v.w * ex;
    float* p = &g_acc[(size_t)dd * D + lane * 4];
    asm volatile("red.global.add.v4.f32 [%0], {%1, %2, %3, %4};"
                 :: "l"(p), "f"(a), "f"(b), "f"(c), "f"(d4) : "memory");
    if (lane == 0) atomicAdd(&g_denom[dd], ex);
}

// ---------------- reciprocal denominators ----------------
__global__ __launch_bounds__(256) void k_invden() {
    int i = blockIdx.x * 256 + threadIdx.x;
    if (i < NN) g_invden[i] = 1.f / (g_denom[i] + 1e-16f);
}

// ---------------- GraphNorm stats over out = acc*invden + gat_bias ----------------
__global__ __launch_bounds__(128) void k_colstats(const float* __restrict__ gb) {
    int c = threadIdx.x;
    float b = gb[c];
    double s = 0.0, q = 0.0;
    for (int r = blockIdx.x; r < NN; r += gridDim.x) {
        float o = g_acc[(size_t)r * D + c] * g_invden[r] + b;
        s += o; q += (double)o * o;
    }
    atomicAdd(&g_cs[c], s);
    atomicAdd(&g_cq[c], q);
}

// ---------------- GraphNorm coefficients: norm(o) = o*A + B ----------------
__global__ void k_finalize(const float* __restrict__ gnw, const float* __restrict__ gnb,
                           const float* __restrict__ gms, const float* __restrict__ gatb) {
    int c = threadIdx.x;
    double m  = g_cs[c] / (double)NN;
    double e2 = g_cq[c] / (double)NN;
    double s  = (double)gms[c];
    double var = e2 - 2.0 * s * m * m + s * s * m * m;   // E[(o - s*m)^2]
    double A = (double)gnw[c] / sqrt(var + 1e-5);
    double B = (double)gnb[c] - s * m * A;
    g_A[c] = (float)A;
    g_B[c] = (float)((double)gatb[c] * A + B);           // gat_bias folded in
}

// ---------------- precompute mixed + norm-scaled final weights ----------------
__global__ __launch_bounds__(256) void k_prep(const float* __restrict__ Wc0, const float* __restrict__ bc0,
                                              const float* __restrict__ Wc1, const float* __restrict__ bc1) {
    __shared__ float2 rr[256];
    int j = blockIdx.x, c = threadIdx.x;
    float w0 = Wc0[j * 256 + c], w1 = Wc1[j * 256 + c];
    float wa = ZA * w1 + ZB * w0;
    float wb = ZA * w0 + ZB * w1;
    float pa = 0.f, pb = 0.f;
    if (c < D) {
        float B = g_B[c], A = g_A[c];
        pa = wa * B; pb = wb * B;
        wa *= A; wb *= A;
    }
    g_Wa[j * 256 + c] = wa;
    g_Wb[j * 256 + c] = wb;
    rr[c] = make_float2(pa, pb);
    __syncthreads();
    for (int off = 128; off > 0; off >>= 1) {
        if (c < off) { rr[c].x += rr[c + off].x; rr[c].y += rr[c + off].y; }
        __syncthreads();
    }
    if (c == 0) {
        g_ba[j] = ZA * bc1[j] + ZB * bc0[j] + rr[0].x;
        g_bb[j] = ZA * bc0[j] + ZB * bc1[j] + rr[0].y;
    }
}

// ---------------- final GEMM over compacted node lists: y = [acc*invden, x_] @ Wsel^T + bsel ----------------
template <int WHICH>
__global__ __launch_bounds__(256) void k_final(const float* __restrict__ x_, float* __restrict__ out) {
    __shared__ int sIdx[64];
    __shared__ __align__(16) float sA[64 * 16];
    __shared__ __align__(16) float sW[16 * 132];
    int cnt = g_cnt[WHICH];
    int base = blockIdx.x * 64;
    if (base >= cnt) return;
    const int*   list = (WHICH == 0) ? g_listT : g_listF;
    const float* W    = (WHICH == 0) ? g_Wa : g_Wb;
    const float* bias = (WHICH == 0) ? g_ba : g_bb;
    int tid = threadIdx.x;
    int warp = tid >> 5, lane = tid & 31;
    int arow = tid >> 2, akq = tid & 3;
    if (tid < 64) sIdx[tid] = (base + tid < cnt) ? list[base + tid] : -1;
    __syncthreads();
    int aidx = sIdx[arow];
    float ainv = (aidx >= 0) ? g_invden[aidx] : 0.f;

    float acc[8][4];
#pragma unroll
    for (int r = 0; r < 8; r++)
#pragma unroll
        for (int i = 0; i < 4; i++) acc[r][i] = 0.f;

    for (int kc = 0; kc < 16; kc++) {
        float4 av = make_float4(0.f, 0.f, 0.f, 0.f);
        if (aidx >= 0) {
            int k0 = kc * 16 + akq * 4;
            if (k0 < D) {
                av = *(const float4*)&g_acc[(size_t)aidx * D + k0];
                av.x *= ainv; av.y *= ainv; av.z *= ainv; av.w *= ainv;
            } else {
                av = *(const float4*)&x_[(size_t)aidx * D + (k0 - D)];
            }
        }
        *(float4*)&sA[arow * 16 + akq * 4] = av;
#pragma unroll
        for (int t = 0; t < 2; t++) {
            int idx = tid + t * 256;
            int j = idx >> 2, kq = idx & 3;
            float4 w = *(const float4*)&W[j * 256 + kc * 16 + kq * 4];
            sW[(kq * 4 + 0) * 132 + j] = w.x; sW[(kq * 4 + 1) * 132 + j] = w.y;
            sW[(kq * 4 + 2) * 132 + j] = w.z; sW[(kq * 4 + 3) * 132 + j] = w.w;
        }
        __syncthreads();
#pragma unroll
        for (int kk = 0; kk < 16; kk++) {
            float4 w = *(const float4*)&sW[kk * 132 + lane * 4];
#pragma unroll
            for (int r = 0; r < 8; r++) {
                float a = sA[(warp * 8 + r) * 16 + kk];
                acc[r][0] += a * w.x; acc[r][1] += a * w.y;
                acc[r][2] += a * w.z; acc[r][3] += a * w.w;
            }
        }
        __syncthreads();
    }
    float4 bv = *(const float4*)&bias[lane * 4];
#pragma unroll
    for (int r = 0; r < 8; r++) {
        int idx2 = sIdx[warp * 8 + r];
        if (idx2 >= 0) {
            *(float4*)&out[(size_t)idx2 * D + lane * 4] =
                make_float4(acc[r][0] + bv.x, acc[r][1] + bv.y,
                            acc[r][2] + bv.z, acc[r][3] + bv.w);
        }
    }
}

// ---------------- launch ----------------
extern "C" void kernel_launch(void* const* d_in, const int* in_sizes, int n_in,
                              void* d_out, int out_size) {
    const float* x_      = (const float*)d_in[0];
    // d_in[1] = edge_attr (unused by reference)
    const float* W_t0    = (const float*)d_in[2];
    const float* b_t0    = (const float*)d_in[3];
    const float* W_t1    = (const float*)d_in[4];
    const float* b_t1    = (const float*)d_in[5];
    const float* gat_W   = (const float*)d_in[6];
    const float* att_src = (const float*)d_in[7];
    const float* att_dst = (const float*)d_in[8];
    const float* gat_b   = (const float*)d_in[9];
    const float* gn_w    = (const float*)d_in[10];
    const float* gn_b    = (const float*)d_in[11];
    const float* gn_ms   = (const float*)d_in[12];
    const float* W_c0    = (const float*)d_in[13];
    const float* b_c0    = (const float*)d_in[14];
    const float* W_c1    = (const float*)d_in[15];
    const float* b_c1    = (const float*)d_in[16];
    const void*  ei      = d_in[17];
    const void*  mask    = d_in[18];
    float* out = (float*)d_out;

    int gb = (NN + 63) / 64;

    k_detect<<<1, 32>>>(ei, mask);
    k_convert<<<(TOTE + 255) / 256, 256>>>(ei, mask);
    k_init<<<2048, 256>>>();
    k_compact<<<(NN + 255) / 256, 256>>>();
    k_tg<<<gb, 256>>>(x_, W_t0, b_t0, W_t1, b_t1, gat_W, att_src, att_dst);
    k_scatter<<<(TOTE + 7) / 8, 256>>>();
    k_invden<<<(NN + 255) / 256, 256>>>();
    k_colstats<<<512, 128>>>(gat_b);
    k_finalize<<<1, 128>>>(gn_w, gn_b, gn_ms, gat_b);
    k_prep<<<128, 256>>>(W_c0, b_c0, W_c1, b_c1);
    k_final<0><<<gb, 256>>>(x_, out);
    k_final<1><<<gb, 256>>>(x_, out);
}

// round 6
// speedup vs baseline: 1.3067x; 1.2352x over previous
#include <cuda_runtime.h>

#define NN 100000
#define EE 1600000
#define TOTE 1700000
#define D 128
#define ZA 0.8f
#define ZB 0.2f
#define NEG 0.2f

// ---------------- scratch (device globals; no runtime allocation) ----------------
__device__ __align__(256) float  g_xp[NN * D];    // GAT-projected features (fp32)
__device__ __align__(256) float  g_acc[NN * D];   // unnormalized GAT aggregation
__device__ __align__(256) float  g_asrc[NN];
__device__ __align__(256) float  g_adst[NN];
__device__ __align__(256) float  g_denom[NN];
__device__ __align__(256) float  g_invden[NN];
__device__ __align__(256) int    g_src[TOTE];
__device__ __align__(256) int    g_dst[TOTE];
__device__ __align__(256) unsigned char g_mask[NN];
__device__ __align__(256) double g_cs[D];
__device__ __align__(256) double g_cq[D];
__device__ __align__(256) float  g_A[D];
__device__ __align__(256) float  g_B[D];
__device__ __align__(256) float  g_tW0[D * D];    // tf32-rounded weight copies
__device__ __align__(256) float  g_tW1[D * D];
__device__ __align__(256) float  g_tGW[D * D];
__device__ __align__(256) float  g_Wa[D * 2 * D]; // combined+scaled weights, tf32-rounded
__device__ __align__(256) float  g_Wb[D * 2 * D];
__device__ __align__(256) float  g_ba[D];
__device__ __align__(256) float  g_bb[D];
__device__ __align__(256) int    g_listT[NN];
__device__ __align__(256) int    g_listF[NN];
__device__            int        g_cnt[2];
__device__            int        g_flags[2];

// ---------------- tf32 helpers ----------------
__device__ __forceinline__ float tff(float f) {
    unsigned u; asm("cvt.rna.tf32.f32 %0, %1;" : "=r"(u) : "f"(f));
    return __uint_as_float(u);
}
__device__ __forceinline__ void mma8(float4& d, const unsigned a[4], unsigned b0, unsigned b1) {
    asm volatile("mma.sync.aligned.m16n8k8.row.col.f32.tf32.tf32.f32 "
                 "{%0,%1,%2,%3},{%4,%5,%6,%7},{%8,%9},{%0,%1,%2,%3};"
                 : "+f"(d.x), "+f"(d.y), "+f"(d.z), "+f"(d.w)
                 : "r"(a[0]), "r"(a[1]), "r"(a[2]), "r"(a[3]), "r"(b0), "r"(b1));
}

// ---------------- dtype detection ----------------
__global__ void k_detect(const void* ei, const void* mask) {
    if (threadIdx.x != 0 || blockIdx.x != 0) return;
    const int* e32 = (const int*)ei;
    int allz = 1;
    for (int i = 1; i < 128; i += 2) if (e32[i] != 0) { allz = 0; break; }
    g_flags[0] = allz;
    const unsigned int* m32 = (const unsigned int*)mask;
    int int_like = 1, float_like = 1;
    for (int i = 0; i < 256; i++) {
        unsigned int w = m32[i];
        if (!(w == 0u || w == 1u)) int_like = 0;
        if (!(w == 0u || w == 0x3F800000u)) float_like = 0;
    }
    g_flags[1] = int_like ? 1 : (float_like ? 2 : 0);
}

// ---------------- normalize inputs ----------------
__global__ __launch_bounds__(256) void k_convert(const void* ei, const void* maskp) {
    int i = blockIdx.x * 256 + threadIdx.x;
    int e64 = g_flags[0], mk = g_flags[1];
    if (i < TOTE) {
        int s, d;
        if (i < EE) {
            if (e64) {
                const long long* e = (const long long*)ei;
                s = (int)e[i]; d = (int)e[EE + i];
            } else {
                const int* e = (const int*)ei;
                s = e[i]; d = e[EE + i];
            }
        } else { s = d = i - EE; }
        g_src[i] = s; g_dst[i] = d;
    }
    if (i < NN) {
        unsigned char m;
        if (mk == 0)      m = ((const unsigned char*)maskp)[i] != 0;
        else if (mk == 1) m = ((const int*)maskp)[i] != 0;
        else              m = ((const float*)maskp)[i] != 0.f;
        g_mask[i] = m;
    }
}

// ---------------- init ----------------
__global__ __launch_bounds__(256) void k_init() {
    size_t i = (size_t)blockIdx.x * blockDim.x + threadIdx.x;
    size_t stride = (size_t)gridDim.x * blockDim.x;
    for (size_t j = i; j < (size_t)NN * D; j += stride) g_acc[j] = 0.f;
    for (size_t j = i; j < NN; j += stride) g_denom[j] = 0.f;
    if (i < D) { g_cs[i] = 0.0; g_cq[i] = 0.0; }
    if (i == 0) { g_cnt[0] = 0; g_cnt[1] = 0; }
}

// ---------------- mask compaction ----------------
__global__ __launch_bounds__(256) void k_compact() {
    int i = blockIdx.x * blockDim.x + threadIdx.x;
    if (i < NN) {
        if (g_mask[i]) g_listT[atomicAdd(&g_cnt[0], 1)] = i;
        else           g_listF[atomicAdd(&g_cnt[1], 1)] = i;
    }
}

// ---------------- pre-convert static weights to tf32 ----------------
__global__ __launch_bounds__(256) void k_cvtw(const float* __restrict__ W0,
                                              const float* __restrict__ W1,
                                              const float* __restrict__ GW) {
    int i = blockIdx.x * 256 + threadIdx.x;
    if (i < D * D) {
        g_tW0[i] = tff(W0[i]);
        g_tW1[i] = tff(W1[i]);
        g_tGW[i] = tff(GW[i]);
    }
}

// ---------------- fused transform+GAT with tf32 tensor cores ----------------
// Stage 1: xmix = mix(relu(x@W1^T+b1), relu(x@W0^T+b0), mask) -> sX (tf32-rounded)
// Stage 2: xp = xmix@GW^T -> g_xp ; a_src/a_dst dots -> g_asrc/g_adst
__global__ __launch_bounds__(256) void k_tg(
    const float* __restrict__ x,
    const float* __restrict__ b0v, const float* __restrict__ b1v,
    const float* __restrict__ att_s, const float* __restrict__ att_d)
{
    __shared__ __align__(16) float sX[64 * 132];  // 33 KB, conflict-free stride
    __shared__ __align__(16) float sA[64 * 12];   // padded stride 12: conflict-free frag loads
    __shared__ __align__(16) float sB0[128 * 8];
    __shared__ __align__(16) float sB1[128 * 8];
    __shared__ float sPS[64], sPD[64];
    __shared__ unsigned char sM[64];

    int tid = threadIdx.x, lane = tid & 31, warp = tid >> 5;
    int wm = warp >> 2, wn = warp & 3;     // 2 x 4 warp grid
    int g = lane >> 2, t = lane & 3;
    int base = blockIdx.x * 64;

    if (tid < 64) {
        sPS[tid] = 0.f; sPD[tid] = 0.f;
        int gr = base + tid;
        sM[tid] = (gr < NN) ? g_mask[gr] : (unsigned char)0;
    }

    float4 acc0[2][4], acc1[2][4];
#pragma unroll
    for (int mt = 0; mt < 2; mt++)
#pragma unroll
        for (int nt = 0; nt < 4; nt++) {
            acc0[mt][nt] = make_float4(0.f, 0.f, 0.f, 0.f);
            acc1[mt][nt] = make_float4(0.f, 0.f, 0.f, 0.f);
        }

    // ---- stage 1: dual tf32 GEMM over K=128 (k8 steps) ----
    for (int kc = 0; kc < 16; kc++) {
        if (tid < 128) {
            int row = tid >> 1, seg = tid & 1, grow = base + row;
            float4 av = make_float4(0.f, 0.f, 0.f, 0.f);
            if (grow < NN) av = *(const float4*)&x[(size_t)grow * D + kc * 8 + seg * 4];
            av.x = tff(av.x); av.y = tff(av.y); av.z = tff(av.z); av.w = tff(av.w);
            *(float4*)&sA[row * 12 + seg * 4] = av;
        }
        {
            int j = tid >> 1, seg = tid & 1;
            *(float4*)&sB0[j * 8 + seg * 4] = *(const float4*)&g_tW0[j * D + kc * 8 + seg * 4];
            *(float4*)&sB1[j * 8 + seg * 4] = *(const float4*)&g_tW1[j * D + kc * 8 + seg * 4];
        }
        __syncthreads();
        unsigned a[2][4];
#pragma unroll
        for (int mt = 0; mt < 2; mt++) {
            int r = wm * 32 + mt * 16 + g;
            a[mt][0] = __float_as_uint(sA[r * 12 + t]);
            a[mt][1] = __float_as_uint(sA[(r + 8) * 12 + t]);
            a[mt][2] = __float_as_uint(sA[r * 12 + t + 4]);
            a[mt][3] = __float_as_uint(sA[(r + 8) * 12 + t + 4]);
        }
#pragma unroll
        for (int nt = 0; nt < 4; nt++) {
            int n = wn * 32 + nt * 8 + g;
            unsigned p0 = __float_as_uint(sB0[n * 8 + t]);
            unsigned p1 = __float_as_uint(sB0[n * 8 + t + 4]);
            unsigned q0 = __float_as_uint(sB1[n * 8 + t]);
            unsigned q1 = __float_as_uint(sB1[n * 8 + t + 4]);
            mma8(acc0[0][nt], a[0], p0, p1);
            mma8(acc0[1][nt], a[1], p0, p1);
            mma8(acc1[0][nt], a[0], q0, q1);
            mma8(acc1[1][nt], a[1], q0, q1);
        }
        __syncthreads();
    }

    // ---- stage-1 epilogue: bias + relu + mix -> sX (tf32-rounded) ----
#pragma unroll
    for (int nt = 0; nt < 4; nt++) {
        int cn = wn * 32 + nt * 8 + t * 2;
        float b0x = b0v[cn], b0y = b0v[cn + 1];
        float b1x = b1v[cn], b1y = b1v[cn + 1];
#pragma unroll
        for (int mt = 0; mt < 2; mt++) {
            int r0 = wm * 32 + mt * 16 + g;
            bool m0 = sM[r0] != 0, m1 = sM[r0 + 8] != 0;
            float4 u0 = acc0[mt][nt], u1 = acc1[mt][nt];
            float v0, v1, ra, rb;
            v0 = fmaxf(u0.x + b0x, 0.f); v1 = fmaxf(u1.x + b1x, 0.f);
            ra = m0 ? (ZA * v1 + ZB * v0) : (ZA * v0 + ZB * v1);
            v0 = fmaxf(u0.y + b0y, 0.f); v1 = fmaxf(u1.y + b1y, 0.f);
            rb = m0 ? (ZA * v1 + ZB * v0) : (ZA * v0 + ZB * v1);
            *(float2*)&sX[r0 * 132 + cn] = make_float2(tff(ra), tff(rb));
            v0 = fmaxf(u0.z + b0x, 0.f); v1 = fmaxf(u1.z + b1x, 0.f);
            ra = m1 ? (ZA * v1 + ZB * v0) : (ZA * v0 + ZB * v1);
            v0 = fmaxf(u0.w + b0y, 0.f); v1 = fmaxf(u1.w + b1y, 0.f);
            rb = m1 ? (ZA * v1 + ZB * v0) : (ZA * v0 + ZB * v1);
            *(float2*)&sX[(r0 + 8) * 132 + cn] = make_float2(tff(ra), tff(rb));
        }
    }
    __syncthreads();

    // ---- stage 2: xp = sX @ GW^T ----
#pragma unroll
    for (int mt = 0; mt < 2; mt++)
#pragma unroll
        for (int nt = 0; nt < 4; nt++)
            acc0[mt][nt] = make_float4(0.f, 0.f, 0.f, 0.f);

    for (int kc = 0; kc < 16; kc++) {
        {
            int j = tid >> 1, seg = tid & 1;
            *(float4*)&sB0[j * 8 + seg * 4] = *(const float4*)&g_tGW[j * D + kc * 8 + seg * 4];
        }
        __syncthreads();
        unsigned a[2][4];
#pragma unroll
        for (int mt = 0; mt < 2; mt++) {
            int r = wm * 32 + mt * 16 + g;
            a[mt][0] = __float_as_uint(sX[r * 132 + kc * 8 + t]);
            a[mt][1] = __float_as_uint(sX[(r + 8) * 132 + kc * 8 + t]);
            a[mt][2] = __float_as_uint(sX[r * 132 + kc * 8 + t + 4]);
            a[mt][3] = __float_as_uint(sX[(r + 8) * 132 + kc * 8 + t + 4]);
        }
#pragma unroll
        for (int nt = 0; nt < 4; nt++) {
            int n = wn * 32 + nt * 8 + g;
            unsigned p0 = __float_as_uint(sB0[n * 8 + t]);
            unsigned p1 = __float_as_uint(sB0[n * 8 + t + 4]);
            mma8(acc0[0][nt], a[0], p0, p1);
            mma8(acc0[1][nt], a[1], p0, p1);
        }
        __syncthreads();
    }

    // ---- stage-2 epilogue: write xp, reduce attention dots ----
    float asx[4][2], adx[4][2];
#pragma unroll
    for (int nt = 0; nt < 4; nt++) {
        int cn = wn * 32 + nt * 8 + t * 2;
        asx[nt][0] = att_s[cn]; asx[nt][1] = att_s[cn + 1];
        adx[nt][0] = att_d[cn]; adx[nt][1] = att_d[cn + 1];
    }
#pragma unroll
    for (int mt = 0; mt < 2; mt++) {
        float p0 = 0.f, p1 = 0.f, q0 = 0.f, q1 = 0.f;
#pragma unroll
        for (int nt = 0; nt < 4; nt++) {
            float4 u = acc0[mt][nt];
            p0 += u.x * asx[nt][0] + u.y * asx[nt][1];
            q0 += u.x * adx[nt][0] + u.y * adx[nt][1];
            p1 += u.z * asx[nt][0] + u.w * asx[nt][1];
            q1 += u.z * adx[nt][0] + u.w * adx[nt][1];
        }
        p0 += __shfl_xor_sync(0xFFFFFFFFu, p0, 1); p0 += __shfl_xor_sync(0xFFFFFFFFu, p0, 2);
        q0 += __shfl_xor_sync(0xFFFFFFFFu, q0, 1); q0 += __shfl_xor_sync(0xFFFFFFFFu, q0, 2);
        p1 += __shfl_xor_sync(0xFFFFFFFFu, p1, 1); p1 += __shfl_xor_sync(0xFFFFFFFFu, p1, 2);
        q1 += __shfl_xor_sync(0xFFFFFFFFu, q1, 1); q1 += __shfl_xor_sync(0xFFFFFFFFu, q1, 2);
        if (t == 0) {
            int r0 = wm * 32 + mt * 16 + g;
            atomicAdd(&sPS[r0], p0);     atomicAdd(&sPD[r0], q0);
            atomicAdd(&sPS[r0 + 8], p1); atomicAdd(&sPD[r0 + 8], q1);
        }
    }
#pragma unroll
    for (int mt = 0; mt < 2; mt++)
#pragma unroll
        for (int nt = 0; nt < 4; nt++) {
            int r0 = base + wm * 32 + mt * 16 + g;
            int cn = wn * 32 + nt * 8 + t * 2;
            float4 u = acc0[mt][nt];
            if (r0 < NN)     *(float2*)&g_xp[(size_t)r0 * D + cn]       = make_float2(u.x, u.y);
            if (r0 + 8 < NN) *(float2*)&g_xp[(size_t)(r0 + 8) * D + cn] = make_float2(u.z, u.w);
        }
    __syncthreads();
    if (tid < 64) {
        int gr = base + tid;
        if (gr < NN) { g_asrc[gr] = sPS[tid]; g_adst[gr] = sPD[tid]; }
    }
}

// ---------------- single-pass edge aggregation ----------------
__global__ __launch_bounds__(256) void k_scatter() {
    int lane = threadIdx.x & 31;
    int e = blockIdx.x * 8 + (threadIdx.x >> 5);
    if (e >= TOTE) return;
    int s = g_src[e], dd = g_dst[e];
    if ((unsigned)s >= NN || (unsigned)dd >= NN) return;
    float al = g_asrc[s] + g_adst[dd];
    al = al > 0.f ? al : NEG * al;
    float ex = expf(al);
    float4 v = *(const float4*)&g_xp[(size_t)s * D + lane * 4];
    float a = v.x * ex, b = v.y * ex, c = v.z * ex, d4 = v.w * ex;
    float* p = &g_acc[(size_t)dd * D + lane * 4];
    asm volatile("red.global.add.v4.f32 [%0], {%1, %2, %3, %4};"
                 :: "l"(p), "f"(a), "f"(b), "f"(c), "f"(d4) : "memory");
    if (lane == 0) atomicAdd(&g_denom[dd], ex);
}

// ---------------- reciprocal denominators ----------------
__global__ __launch_bounds__(256) void k_invden() {
    int i = blockIdx.x * 256 + threadIdx.x;
    if (i < NN) g_invden[i] = 1.f / (g_denom[i] + 1e-16f);
}

// ---------------- GraphNorm stats over out = acc*invden + gat_bias ----------------
__global__ __launch_bounds__(128) void k_colstats(const float* __restrict__ gb) {
    int c = threadIdx.x;
    float b = gb[c];
    double s = 0.0, q = 0.0;
    for (int r = blockIdx.x; r < NN; r += gridDim.x) {
        float o = g_acc[(size_t)r * D + c] * g_invden[r] + b;
        s += o; q += (double)o * o;
    }
    atomicAdd(&g_cs[c], s);
    atomicAdd(&g_cq[c], q);
}

// ---------------- GraphNorm coefficients: norm(o) = o*A + B ----------------
__global__ void k_finalize(const float* __restrict__ gnw, const float* __restrict__ gnb,
                           const float* __restrict__ gms, const float* __restrict__ gatb) {
    int c = threadIdx.x;
    double m  = g_cs[c] / (double)NN;
    double e2 = g_cq[c] / (double)NN;
    double s  = (double)gms[c];
    double var = e2 - 2.0 * s * m * m + s * s * m * m;
    double A = (double)gnw[c] / sqrt(var + 1e-5);
    double B = (double)gnb[c] - s * m * A;
    g_A[c] = (float)A;
    g_B[c] = (float)((double)gatb[c] * A + B);
}

// ---------------- precompute mixed + norm-scaled final weights (tf32-rounded) ----------------
__global__ __launch_bounds__(256) void k_prep(const float* __restrict__ Wc0, const float* __restrict__ bc0,
                                              const float* __restrict__ Wc1, const float* __restrict__ bc1) {
    __shared__ float2 rr[256];
    int j = blockIdx.x, c = threadIdx.x;
    float w0 = Wc0[j * 256 + c], w1 = Wc1[j * 256 + c];
    float wa = ZA * w1 + ZB * w0;
    float wb = ZA * w0 + ZB * w1;
    float pa = 0.f, pb = 0.f;
    if (c < D) {
        float Bv = g_B[c], A = g_A[c];
        pa = wa * Bv; pb = wb * Bv;
        wa *= A; wb *= A;
    }
    g_Wa[j * 256 + c] = tff(wa);
    g_Wb[j * 256 + c] = tff(wb);
    rr[c] = make_float2(pa, pb);
    __syncthreads();
    for (int off = 128; off > 0; off >>= 1) {
        if (c < off) { rr[c].x += rr[c + off].x; rr[c].y += rr[c + off].y; }
        __syncthreads();
    }
    if (c == 0) {
        g_ba[j] = ZA * bc1[j] + ZB * bc0[j] + rr[0].x;
        g_bb[j] = ZA * bc0[j] + ZB * bc1[j] + rr[0].y;
    }
}

// ---------------- final GEMM (tf32) over compacted node lists ----------------
template <int WHICH>
__global__ __launch_bounds__(256) void k_final(const float* __restrict__ x_, float* __restrict__ out) {
    __shared__ __align__(16) float sA[64 * 12];
    __shared__ __align__(16) float sB[128 * 8];
    __shared__ int   sIdx[64];
    __shared__ float sInv[64];
    int cnt = g_cnt[WHICH];
    int base = blockIdx.x * 64;
    if (base >= cnt) return;
    const int*   list = (WHICH == 0) ? g_listT : g_listF;
    const float* W    = (WHICH == 0) ? g_Wa : g_Wb;
    const float* bias = (WHICH == 0) ? g_ba : g_bb;
    int tid = threadIdx.x, lane = tid & 31, warp = tid >> 5;
    int wm = warp >> 2, wn = warp & 3;
    int g = lane >> 2, t = lane & 3;
    if (tid < 64) {
        int idx = (base + tid < cnt) ? list[base + tid] : -1;
        sIdx[tid] = idx;
        sInv[tid] = (idx >= 0) ? g_invden[idx] : 0.f;
    }
    __syncthreads();

    float4 acc[2][4];
#pragma unroll
    for (int mt = 0; mt < 2; mt++)
#pragma unroll
        for (int nt = 0; nt < 4; nt++) acc[mt][nt] = make_float4(0.f, 0.f, 0.f, 0.f);

    for (int kc = 0; kc < 32; kc++) {
        if (tid < 128) {
            int row = tid >> 1, seg = tid & 1;
            int aidx = sIdx[row];
            int k0 = kc * 8 + seg * 4;
            float4 av = make_float4(0.f, 0.f, 0.f, 0.f);
            if (aidx >= 0) {
                if (k0 < D) {
                    av = *(const float4*)&g_acc[(size_t)aidx * D + k0];
                    float iv = sInv[row];
                    av.x *= iv; av.y *= iv; av.z *= iv; av.w *= iv;
                } else {
                    av = *(const float4*)&x_[(size_t)aidx * D + (k0 - D)];
                }
            }
            av.x = tff(av.x); av.y = tff(av.y); av.z = tff(av.z); av.w = tff(av.w);
            *(float4*)&sA[row * 12 + seg * 4] = av;
        }
        {
            int j = tid >> 1, seg = tid & 1;
            *(float4*)&sB[j * 8 + seg * 4] = *(const float4*)&W[j * 256 + kc * 8 + seg * 4];
        }
        __syncthreads();
        unsigned a[2][4];
#pragma unroll
        for (int mt = 0; mt < 2; mt++) {
            int r = wm * 32 + mt * 16 + g;
            a[mt][0] = __float_as_uint(sA[r * 12 + t]);
            a[mt][1] = __float_as_uint(sA[(r + 8) * 12 + t]);
            a[mt][2] = __float_as_uint(sA[r * 12 + t + 4]);
            a[mt][3] = __float_as_uint(sA[(r + 8) * 12 + t + 4]);
        }
#pragma unroll
        for (int nt = 0; nt < 4; nt++) {
            int n = wn * 32 + nt * 8 + g;
            unsigned p0 = __float_as_uint(sB[n * 8 + t]);
            unsigned p1 = __float_as_uint(sB[n * 8 + t + 4]);
            mma8(acc[0][nt], a[0], p0, p1);
            mma8(acc[1][nt], a[1], p0, p1);
        }
        __syncthreads();
    }
#pragma unroll
    for (int nt = 0; nt < 4; nt++) {
        int cn = wn * 32 + nt * 8 + t * 2;
        float bx = bias[cn], by = bias[cn + 1];
#pragma unroll
        for (int mt = 0; mt < 2; mt++) {
            int r = wm * 32 + mt * 16 + g;
            int i0 = sIdx[r], i1 = sIdx[r + 8];
            float4 u = acc[mt][nt];
            if (i0 >= 0) *(float2*)&out[(size_t)i0 * D + cn] = make_float2(u.x + bx, u.y + by);
            if (i1 >= 0) *(float2*)&out[(size_t)i1 * D + cn] = make_float2(u.z + bx, u.w + by);
        }
    }
}

// ---------------- launch ----------------
extern "C" void kernel_launch(void* const* d_in, const int* in_sizes, int n_in,
                              void* d_out, int out_size) {
    const float* x_      = (const float*)d_in[0];
    const float* W_t0    = (const float*)d_in[2];
    const float* b_t0    = (const float*)d_in[3];
    const float* W_t1    = (const float*)d_in[4];
    const float* b_t1    = (const float*)d_in[5];
    const float* gat_W   = (const float*)d_in[6];
    const float* att_src = (const float*)d_in[7];
    const float* att_dst = (const float*)d_in[8];
    const float* gat_b   = (const float*)d_in[9];
    const float* gn_w    = (const float*)d_in[10];
    const float* gn_b    = (const float*)d_in[11];
    const float* gn_ms   = (const float*)d_in[12];
    const float* W_c0    = (const float*)d_in[13];
    const float* b_c0    = (const float*)d_in[14];
    const float* W_c1    = (const float*)d_in[15];
    const float* b_c1    = (const float*)d_in[16];
    const void*  ei      = d_in[17];
    const void*  mask    = d_in[18];
    float* out = (float*)d_out;

    int gb = (NN + 63) / 64;

    k_detect<<<1, 32>>>(ei, mask);
    k_convert<<<(TOTE + 255) / 256, 256>>>(ei, mask);
    k_init<<<2048, 256>>>();
    k_compact<<<(NN + 255) / 256, 256>>>();
    k_cvtw<<<(D * D + 255) / 256, 256>>>(W_t0, W_t1, gat_W);
    k_tg<<<gb, 256>>>(x_, b_t0, b_t1, att_src, att_dst);
    k_scatter<<<(TOTE + 7) / 8, 256>>>();
    k_invden<<<(NN + 255) / 256, 256>>>();
    k_colstats<<<512, 128>>>(gat_b);
    k_finalize<<<1, 128>>>(gn_w, gn_b, gn_ms, gat_b);
    k_prep<<<128, 256>>>(W_c0, b_c0, W_c1, b_c1);
    k_final<0><<<gb, 256>>>(x_, out);
    k_final<1><<<gb, 256>>>(x_, out);
}

// round 7
// speedup vs baseline: 1.3104x; 1.0029x over previous
#include <cuda_runtime.h>

#define NN 100000
#define EE 1600000
#define TOTE 1700000
#define D 128
#define ZA 0.8f
#define ZB 0.2f
#define NEG 0.2f

// ---------------- scratch (device globals; no runtime allocation) ----------------
__device__ __align__(256) float  g_xp[NN * D];    // GAT-projected features (fp32)
__device__ __align__(256) float  g_acc[NN * D];   // unnormalized GAT aggregation
__device__ __align__(256) float  g_asrc[NN];
__device__ __align__(256) float  g_adst[NN];
__device__ __align__(256) float  g_denom[NN];
__device__ __align__(256) float  g_invden[NN];
__device__ __align__(256) int    g_src[TOTE];
__device__ __align__(256) int    g_dst[TOTE];
__device__ __align__(256) unsigned char g_mask[NN];
__device__ __align__(256) double g_cs[D];
__device__ __align__(256) double g_cq[D];
__device__ __align__(256) float  g_A[D];
__device__ __align__(256) float  g_B[D];
__device__ __align__(256) float  g_tW0[D * D];    // tf32-rounded weight copies
__device__ __align__(256) float  g_tW1[D * D];
__device__ __align__(256) float  g_tGW[D * D];
__device__ __align__(256) float  g_Wa[D * 2 * D]; // combined+scaled weights, tf32-rounded
__device__ __align__(256) float  g_Wb[D * 2 * D];
__device__ __align__(256) float  g_ba[D];
__device__ __align__(256) float  g_bb[D];
__device__ __align__(256) int    g_listT[NN];
__device__ __align__(256) int    g_listF[NN];
__device__            int        g_cnt[2];
__device__            int        g_flags[2];

// ---------------- tf32 helpers ----------------
__device__ __forceinline__ float tff(float f) {
    unsigned u; asm("cvt.rna.tf32.f32 %0, %1;" : "=r"(u) : "f"(f));
    return __uint_as_float(u);
}
__device__ __forceinline__ void mma8(float4& d, const unsigned a[4], unsigned b0, unsigned b1) {
    asm volatile("mma.sync.aligned.m16n8k8.row.col.f32.tf32.tf32.f32 "
                 "{%0,%1,%2,%3},{%4,%5,%6,%7},{%8,%9},{%0,%1,%2,%3};"
                 : "+f"(d.x), "+f"(d.y), "+f"(d.z), "+f"(d.w)
                 : "r"(a[0]), "r"(a[1]), "r"(a[2]), "r"(a[3]), "r"(b0), "r"(b1));
}

// ---------------- dtype detection ----------------
__global__ void k_detect(const void* ei, const void* mask) {
    if (threadIdx.x != 0 || blockIdx.x != 0) return;
    const int* e32 = (const int*)ei;
    int allz = 1;
    for (int i = 1; i < 128; i += 2) if (e32[i] != 0) { allz = 0; break; }
    g_flags[0] = allz;
    const unsigned int* m32 = (const unsigned int*)mask;
    int int_like = 1, float_like = 1;
    for (int i = 0; i < 256; i++) {
        unsigned int w = m32[i];
        if (!(w == 0u || w == 1u)) int_like = 0;
        if (!(w == 0u || w == 0x3F800000u)) float_like = 0;
    }
    g_flags[1] = int_like ? 1 : (float_like ? 2 : 0);
}

// ---------------- normalize inputs ----------------
__global__ __launch_bounds__(256) void k_convert(const void* ei, const void* maskp) {
    int i = blockIdx.x * 256 + threadIdx.x;
    int e64 = g_flags[0], mk = g_flags[1];
    if (i < TOTE) {
        int s, d;
        if (i < EE) {
            if (e64) {
                const long long* e = (const long long*)ei;
                s = (int)e[i]; d = (int)e[EE + i];
            } else {
                const int* e = (const int*)ei;
                s = e[i]; d = e[EE + i];
            }
        } else { s = d = i - EE; }
        g_src[i] = s; g_dst[i] = d;
    }
    if (i < NN) {
        unsigned char m;
        if (mk == 0)      m = ((const unsigned char*)maskp)[i] != 0;
        else if (mk == 1) m = ((const int*)maskp)[i] != 0;
        else              m = ((const float*)maskp)[i] != 0.f;
        g_mask[i] = m;
    }
}

// ---------------- init ----------------
__global__ __launch_bounds__(256) void k_init() {
    size_t i = (size_t)blockIdx.x * blockDim.x + threadIdx.x;
    size_t stride = (size_t)gridDim.x * blockDim.x;
    for (size_t j = i; j < (size_t)NN * D; j += stride) g_acc[j] = 0.f;
    for (size_t j = i; j < NN; j += stride) g_denom[j] = 0.f;
    if (i < D) { g_cs[i] = 0.0; g_cq[i] = 0.0; }
    if (i == 0) { g_cnt[0] = 0; g_cnt[1] = 0; }
}

// ---------------- mask compaction ----------------
__global__ __launch_bounds__(256) void k_compact() {
    int i = blockIdx.x * blockDim.x + threadIdx.x;
    if (i < NN) {
        if (g_mask[i]) g_listT[atomicAdd(&g_cnt[0], 1)] = i;
        else           g_listF[atomicAdd(&g_cnt[1], 1)] = i;
    }
}

// ---------------- pre-convert static weights to tf32 ----------------
__global__ __launch_bounds__(256) void k_cvtw(const float* __restrict__ W0,
                                              const float* __restrict__ W1,
                                              const float* __restrict__ GW) {
    int i = blockIdx.x * 256 + threadIdx.x;
    if (i < D * D) {
        g_tW0[i] = tff(W0[i]);
        g_tW1[i] = tff(W1[i]);
        g_tGW[i] = tff(GW[i]);
    }
}

// ---------------- fused transform+GAT with tf32 tensor cores ----------------
// Stage 1: xmix = mix(relu(x@W1^T+b1), relu(x@W0^T+b0), mask) -> sX (tf32-rounded)
// Stage 2: xp = xmix@GW^T -> g_xp ; a_src/a_dst dots -> g_asrc/g_adst
__global__ __launch_bounds__(256) void k_tg(
    const float* __restrict__ x,
    const float* __restrict__ b0v, const float* __restrict__ b1v,
    const float* __restrict__ att_s, const float* __restrict__ att_d)
{
    __shared__ __align__(16) float sX[64 * 132];  // 33 KB, conflict-free stride
    __shared__ __align__(16) float sA[64 * 12];   // padded stride 12: conflict-free frag loads
    __shared__ __align__(16) float sB0[128 * 8];
    __shared__ __align__(16) float sB1[128 * 8];
    __shared__ float sPS[64], sPD[64];
    __shared__ unsigned char sM[64];

    int tid = threadIdx.x, lane = tid & 31, warp = tid >> 5;
    int wm = warp >> 2, wn = warp & 3;     // 2 x 4 warp grid
    int g = lane >> 2, t = lane & 3;
    int base = blockIdx.x * 64;

    if (tid < 64) {
        sPS[tid] = 0.f; sPD[tid] = 0.f;
        int gr = base + tid;
        sM[tid] = (gr < NN) ? g_mask[gr] : (unsigned char)0;
    }

    float4 acc0[2][4], acc1[2][4];
#pragma unroll
    for (int mt = 0; mt < 2; mt++)
#pragma unroll
        for (int nt = 0; nt < 4; nt++) {
            acc0[mt][nt] = make_float4(0.f, 0.f, 0.f, 0.f);
            acc1[mt][nt] = make_float4(0.f, 0.f, 0.f, 0.f);
        }

    // ---- stage 1: dual tf32 GEMM over K=128 (k8 steps) ----
    for (int kc = 0; kc < 16; kc++) {
        if (tid < 128) {
            int row = tid >> 1, seg = tid & 1, grow = base + row;
            float4 av = make_float4(0.f, 0.f, 0.f, 0.f);
            if (grow < NN) av = *(const float4*)&x[(size_t)grow * D + kc * 8 + seg * 4];
            av.x = tff(av.x); av.y = tff(av.y); av.z = tff(av.z); av.w = tff(av.w);
            *(float4*)&sA[row * 12 + seg * 4] = av;
        }
        {
            int j = tid >> 1, seg = tid & 1;
            *(float4*)&sB0[j * 8 + seg * 4] = *(const float4*)&g_tW0[j * D + kc * 8 + seg * 4];
            *(float4*)&sB1[j * 8 + seg * 4] = *(const float4*)&g_tW1[j * D + kc * 8 + seg * 4];
        }
        __syncthreads();
        unsigned a[2][4];
#pragma unroll
        for (int mt = 0; mt < 2; mt++) {
            int r = wm * 32 + mt * 16 + g;
            a[mt][0] = __float_as_uint(sA[r * 12 + t]);
            a[mt][1] = __float_as_uint(sA[(r + 8) * 12 + t]);
            a[mt][2] = __float_as_uint(sA[r * 12 + t + 4]);
            a[mt][3] = __float_as_uint(sA[(r + 8) * 12 + t + 4]);
        }
#pragma unroll
        for (int nt = 0; nt < 4; nt++) {
            int n = wn * 32 + nt * 8 + g;
            unsigned p0 = __float_as_uint(sB0[n * 8 + t]);
            unsigned p1 = __float_as_uint(sB0[n * 8 + t + 4]);
            unsigned q0 = __float_as_uint(sB1[n * 8 + t]);
            unsigned q1 = __float_as_uint(sB1[n * 8 + t + 4]);
            mma8(acc0[0][nt], a[0], p0, p1);
            mma8(acc0[1][nt], a[1], p0, p1);
            mma8(acc1[0][nt], a[0], q0, q1);
            mma8(acc1[1][nt], a[1], q0, q1);
        }
        __syncthreads();
    }

    // ---- stage-1 epilogue: bias + relu + mix -> sX (tf32-rounded) ----
#pragma unroll
    for (int nt = 0; nt < 4; nt++) {
        int cn = wn * 32 + nt * 8 + t * 2;
        float b0x = b0v[cn], b0y = b0v[cn + 1];
        float b1x = b1v[cn], b1y = b1v[cn + 1];
#pragma unroll
        for (int mt = 0; mt < 2; mt++) {
            int r0 = wm * 32 + mt * 16 + g;
            bool m0 = sM[r0] != 0, m1 = sM[r0 + 8] != 0;
            float4 u0 = acc0[mt][nt], u1 = acc1[mt][nt];
            float v0, v1, ra, rb;
            v0 = fmaxf(u0.x + b0x, 0.f); v1 = fmaxf(u1.x + b1x, 0.f);
            ra = m0 ? (ZA * v1 + ZB * v0) : (ZA * v0 + ZB * v1);
            v0 = fmaxf(u0.y + b0y, 0.f); v1 = fmaxf(u1.y + b1y, 0.f);
            rb = m0 ? (ZA * v1 + ZB * v0) : (ZA * v0 + ZB * v1);
            *(float2*)&sX[r0 * 132 + cn] = make_float2(tff(ra), tff(rb));
            v0 = fmaxf(u0.z + b0x, 0.f); v1 = fmaxf(u1.z + b1x, 0.f);
            ra = m1 ? (ZA * v1 + ZB * v0) : (ZA * v0 + ZB * v1);
            v0 = fmaxf(u0.w + b0y, 0.f); v1 = fmaxf(u1.w + b1y, 0.f);
            rb = m1 ? (ZA * v1 + ZB * v0) : (ZA * v0 + ZB * v1);
            *(float2*)&sX[(r0 + 8) * 132 + cn] = make_float2(tff(ra), tff(rb));
        }
    }
    __syncthreads();

    // ---- stage 2: xp = sX @ GW^T ----
#pragma unroll
    for (int mt = 0; mt < 2; mt++)
#pragma unroll
        for (int nt = 0; nt < 4; nt++)
            acc0[mt][nt] = make_float4(0.f, 0.f, 0.f, 0.f);

    for (int kc = 0; kc < 16; kc++) {
        {
            int j = tid >> 1, seg = tid & 1;
            *(float4*)&sB0[j * 8 + seg * 4] = *(const float4*)&g_tGW[j * D + kc * 8 + seg * 4];
        }
        __syncthreads();
        unsigned a[2][4];
#pragma unroll
        for (int mt = 0; mt < 2; mt++) {
            int r = wm * 32 + mt * 16 + g;
            a[mt][0] = __float_as_uint(sX[r * 132 + kc * 8 + t]);
            a[mt][1] = __float_as_uint(sX[(r + 8) * 132 + kc * 8 + t]);
            a[mt][2] = __float_as_uint(sX[r * 132 + kc * 8 + t + 4]);
            a[mt][3] = __float_as_uint(sX[(r + 8) * 132 + kc * 8 + t + 4]);
        }
#pragma unroll
        for (int nt = 0; nt < 4; nt++) {
            int n = wn * 32 + nt * 8 + g;
            unsigned p0 = __float_as_uint(sB0[n * 8 + t]);
            unsigned p1 = __float_as_uint(sB0[n * 8 + t + 4]);
            mma8(acc0[0][nt], a[0], p0, p1);
            mma8(acc0[1][nt], a[1], p0, p1);
        }
        __syncthreads();
    }

    // ---- stage-2 epilogue: write xp, reduce attention dots ----
    float asx[4][2], adx[4][2];
#pragma unroll
    for (int nt = 0; nt < 4; nt++) {
        int cn = wn * 32 + nt * 8 + t * 2;
        asx[nt][0] = att_s[cn]; asx[nt][1] = att_s[cn + 1];
        adx[nt][0] = att_d[cn]; adx[nt][1] = att_d[cn + 1];
    }
#pragma unroll
    for (int mt = 0; mt < 2; mt++) {
        float p0 = 0.f, p1 = 0.f, q0 = 0.f, q1 = 0.f;
#pragma unroll
        for (int nt = 0; nt < 4; nt++) {
            float4 u = acc0[mt][nt];
            p0 += u.x * asx[nt][0] + u.y * asx[nt][1];
            q0 += u.x * adx[nt][0] + u.y * adx[nt][1];
            p1 += u.z * asx[nt][0] + u.w * asx[nt][1];
            q1 += u.z * adx[nt][0] + u.w * adx[nt][1];
        }
        p0 += __shfl_xor_sync(0xFFFFFFFFu, p0, 1); p0 += __shfl_xor_sync(0xFFFFFFFFu, p0, 2);
        q0 += __shfl_xor_sync(0xFFFFFFFFu, q0, 1); q0 += __shfl_xor_sync(0xFFFFFFFFu, q0, 2);
        p1 += __shfl_xor_sync(0xFFFFFFFFu, p1, 1); p1 += __shfl_xor_sync(0xFFFFFFFFu, p1, 2);
        q1 += __shfl_xor_sync(0xFFFFFFFFu, q1, 1); q1 += __shfl_xor_sync(0xFFFFFFFFu, q1, 2);
        if (t == 0) {
            int r0 = wm * 32 + mt * 16 + g;
            atomicAdd(&sPS[r0], p0);     atomicAdd(&sPD[r0], q0);
            atomicAdd(&sPS[r0 + 8], p1); atomicAdd(&sPD[r0 + 8], q1);
        }
    }
#pragma unroll
    for (int mt = 0; mt < 2; mt++)
#pragma unroll
        for (int nt = 0; nt < 4; nt++) {
            int r0 = base + wm * 32 + mt * 16 + g;
            int cn = wn * 32 + nt * 8 + t * 2;
            float4 u = acc0[mt][nt];
            if (r0 < NN)     *(float2*)&g_xp[(size_t)r0 * D + cn]       = make_float2(u.x, u.y);
            if (r0 + 8 < NN) *(float2*)&g_xp[(size_t)(r0 + 8) * D + cn] = make_float2(u.z, u.w);
        }
    __syncthreads();
    if (tid < 64) {
        int gr = base + tid;
        if (gr < NN) { g_asrc[gr] = sPS[tid]; g_adst[gr] = sPD[tid]; }
    }
}

// ---------------- single-pass edge aggregation ----------------
__global__ __launch_bounds__(256) void k_scatter() {
    int lane = threadIdx.x & 31;
    int e = blockIdx.x * 8 + (threadIdx.x >> 5);
    if (e >= TOTE) return;
    int s = g_src[e], dd = g_dst[e];
    if ((unsigned)s >= NN || (unsigned)dd >= NN) return;
    float al = g_asrc[s] + g_adst[dd];
    al = al > 0.f ? al : NEG * al;
    float ex = expf(al);
    float4 v = *(const float4*)&g_xp[(size_t)s * D + lane * 4];
    float a = v.x * ex, b = v.y * ex, c = v.z * ex, d4 = v.w * ex;
    float* p = &g_acc[(size_t)dd * D + lane * 4];
    asm volatile("red.global.add.v4.f32 [%0], {%1, %2, %3, %4};"
                 :: "l"(p), "f"(a), "f"(b), "f"(c), "f"(d4) : "memory");
    if (lane == 0) atomicAdd(&g_denom[dd], ex);
}

// ---------------- reciprocal denominators ----------------
__global__ __launch_bounds__(256) void k_invden() {
    int i = blockIdx.x * 256 + threadIdx.x;
    if (i < NN) g_invden[i] = 1.f / (g_denom[i] + 1e-16f);
}

// ---------------- GraphNorm stats over out = acc*invden + gat_bias ----------------
__global__ __launch_bounds__(128) void k_colstats(const float* __restrict__ gb) {
    int c = threadIdx.x;
    float b = gb[c];
    double s = 0.0, q = 0.0;
    for (int r = blockIdx.x; r < NN; r += gridDim.x) {
        float o = g_acc[(size_t)r * D + c] * g_invden[r] + b;
        s += o; q += (double)o * o;
    }
    atomicAdd(&g_cs[c], s);
    atomicAdd(&g_cq[c], q);
}

// ---------------- GraphNorm coefficients: norm(o) = o*A + B ----------------
__global__ void k_finalize(const float* __restrict__ gnw, const float* __restrict__ gnb,
                           const float* __restrict__ gms, const float* __restrict__ gatb) {
    int c = threadIdx.x;
    double m  = g_cs[c] / (double)NN;
    double e2 = g_cq[c] / (double)NN;
    double s  = (double)gms[c];
    double var = e2 - 2.0 * s * m * m + s * s * m * m;
    double A = (double)gnw[c] / sqrt(var + 1e-5);
    double B = (double)gnb[c] - s * m * A;
    g_A[c] = (float)A;
    g_B[c] = (float)((double)gatb[c] * A + B);
}

// ---------------- precompute mixed + norm-scaled final weights (tf32-rounded) ----------------
__global__ __launch_bounds__(256) void k_prep(const float* __restrict__ Wc0, const float* __restrict__ bc0,
                                              const float* __restrict__ Wc1, const float* __restrict__ bc1) {
    __shared__ float2 rr[256];
    int j = blockIdx.x, c = threadIdx.x;
    float w0 = Wc0[j * 256 + c], w1 = Wc1[j * 256 + c];
    float wa = ZA * w1 + ZB * w0;
    float wb = ZA * w0 + ZB * w1;
    float pa = 0.f, pb = 0.f;
    if (c < D) {
        float Bv = g_B[c], A = g_A[c];
        pa = wa * Bv; pb = wb * Bv;
        wa *= A; wb *= A;
    }
    g_Wa[j * 256 + c] = tff(wa);
    g_Wb[j * 256 + c] = tff(wb);
    rr[c] = make_float2(pa, pb);
    __syncthreads();
    for (int off = 128; off > 0; off >>= 1) {
        if (c < off) { rr[c].x += rr[c + off].x; rr[c].y += rr[c + off].y; }
        __syncthreads();
    }
    if (c == 0) {
        g_ba[j] = ZA * bc1[j] + ZB * bc0[j] + rr[0].x;
        g_bb[j] = ZA * bc0[j] + ZB * bc1[j] + rr[0].y;
    }
}

// ---------------- final GEMM (tf32) over compacted node lists ----------------
template <int WHICH>
__global__ __launch_bounds__(256) void k_final(const float* __restrict__ x_, float* __restrict__ out) {
    __shared__ __align__(16) float sA[64 * 12];
    __shared__ __align__(16) float sB[128 * 8];
    __shared__ int   sIdx[64];
    __shared__ float sInv[64];
    int cnt = g_cnt[WHICH];
    int base = blockIdx.x * 64;
    if (base >= cnt) return;
    const int*   list = (WHICH == 0) ? g_listT : g_listF;
    const float* W    = (WHICH == 0) ? g_Wa : g_Wb;
    const float* bias = (WHICH == 0) ? g_ba : g_bb;
    int tid = threadIdx.x, lane = tid & 31, warp = tid >> 5;
    int wm = warp >> 2, wn = warp & 3;
    int g = lane >> 2, t = lane & 3;
    if (tid < 64) {
        int idx = (base + tid < cnt) ? list[base + tid] : -1;
        sIdx[tid] = idx;
        sInv[tid] = (idx >= 0) ? g_invden[idx] : 0.f;
    }
    __syncthreads();

    float4 acc[2][4];
#pragma unroll
    for (int mt = 0; mt < 2; mt++)
#pragma unroll
        for (int nt = 0; nt < 4; nt++) acc[mt][nt] = make_float4(0.f, 0.f, 0.f, 0.f);

    for (int kc = 0; kc < 32; kc++) {
        if (tid < 128) {
            int row = tid >> 1, seg = tid & 1;
            int aidx = sIdx[row];
            int k0 = kc * 8 + seg * 4;
            float4 av = make_float4(0.f, 0.f, 0.f, 0.f);
            if (aidx >= 0) {
                if (k0 < D) {
                    av = *(const float4*)&g_acc[(size_t)aidx * D + k0];
                    float iv = sInv[row];
                    av.x *= iv; av.y *= iv; av.z *= iv; av.w *= iv;
                } else {
                    av = *(const float4*)&x_[(size_t)aidx * D + (k0 - D)];
                }
            }
            av.x = tff(av.x); av.y = tff(av.y); av.z = tff(av.z); av.w = tff(av.w);
            *(float4*)&sA[row * 12 + seg * 4] = av;
        }
        {
            int j = tid >> 1, seg = tid & 1;
            *(float4*)&sB[j * 8 + seg * 4] = *(const float4*)&W[j * 256 + kc * 8 + seg * 4];
        }
        __syncthreads();
        unsigned a[2][4];
#pragma unroll
        for (int mt = 0; mt < 2; mt++) {
            int r = wm * 32 + mt * 16 + g;
            a[mt][0] = __float_as_uint(sA[r * 12 + t]);
            a[mt][1] = __float_as_uint(sA[(r + 8) * 12 + t]);
            a[mt][2] = __float_as_uint(sA[r * 12 + t + 4]);
            a[mt][3] = __float_as_uint(sA[(r + 8) * 12 + t + 4]);
        }
#pragma unroll
        for (int nt = 0; nt < 4; nt++) {
            int n = wn * 32 + nt * 8 + g;
            unsigned p0 = __float_as_uint(sB[n * 8 + t]);
            unsigned p1 = __float_as_uint(sB[n * 8 + t + 4]);
            mma8(acc[0][nt], a[0], p0, p1);
            mma8(acc[1][nt], a[1], p0, p1);
        }
        __syncthreads();
    }
#pragma unroll
    for (int nt = 0; nt < 4; nt++) {
        int cn = wn * 32 + nt * 8 + t * 2;
        float bx = bias[cn], by = bias[cn + 1];
#pragma unroll
        for (int mt = 0; mt < 2; mt++) {
            int r = wm * 32 + mt * 16 + g;
            int i0 = sIdx[r], i1 = sIdx[r + 8];
            float4 u = acc[mt][nt];
            if (i0 >= 0) *(float2*)&out[(size_t)i0 * D + cn] = make_float2(u.x + bx, u.y + by);
            if (i1 >= 0) *(float2*)&out[(size_t)i1 * D + cn] = make_float2(u.z + bx, u.w + by);
        }
    }
}

// ---------------- launch ----------------
extern "C" void kernel_launch(void* const* d_in, const int* in_sizes, int n_in,
                              void* d_out, int out_size) {
    const float* x_      = (const float*)d_in[0];
    const float* W_t0    = (const float*)d_in[2];
    const float* b_t0    = (const float*)d_in[3];
    const float* W_t1    = (const float*)d_in[4];
    const float* b_t1    = (const float*)d_in[5];
    const float* gat_W   = (const float*)d_in[6];
    const float* att_src = (const float*)d_in[7];
    const float* att_dst = (const float*)d_in[8];
    const float* gat_b   = (const float*)d_in[9];
    const float* gn_w    = (const float*)d_in[10];
    const float* gn_b    = (const float*)d_in[11];
    const float* gn_ms   = (const float*)d_in[12];
    const float* W_c0    = (const float*)d_in[13];
    const float* b_c0    = (const float*)d_in[14];
    const float* W_c1    = (const float*)d_in[15];
    const float* b_c1    = (const float*)d_in[16];
    const void*  ei      = d_in[17];
    const void*  mask    = d_in[18];
    float* out = (float*)d_out;

    int gb = (NN + 63) / 64;

    k_detect<<<1, 32>>>(ei, mask);
    k_convert<<<(TOTE + 255) / 256, 256>>>(ei, mask);
    k_init<<<2048, 256>>>();
    k_compact<<<(NN + 255) / 256, 256>>>();
    k_cvtw<<<(D * D + 255) / 256, 256>>>(W_t0, W_t1, gat_W);
    k_tg<<<gb, 256>>>(x_, b_t0, b_t1, att_src, att_dst);
    k_scatter<<<(TOTE + 7) / 8, 256>>>();
    k_invden<<<(NN + 255) / 256, 256>>>();
    k_colstats<<<512, 128>>>(gat_b);
    k_finalize<<<1, 128>>>(gn_w, gn_b, gn_ms, gat_b);
    k_prep<<<128, 256>>>(W_c0, b_c0, W_c1, b_c1);
    k_final<0><<<gb, 256>>>(x_, out);
    k_final<1><<<gb, 256>>>(x_, out);
}

// round 8
// speedup vs baseline: 1.3499x; 1.0301x over previous
#include <cuda_runtime.h>

#define NN 100000
#define EE 1600000
#define TOTE 1700000
#define D 128
#define ZA 0.8f
#define ZB 0.2f
#define NEG 0.2f
#define NBLK 98   // ceil(NN / 1024)

// ---------------- scratch (device globals; no runtime allocation) ----------------
__device__ __align__(256) float  g_xp[NN * D];    // GAT-projected features (fp32, tf32x3-accurate)
__device__ __align__(256) float  g_acc[NN * D];   // normalized aggregation output
__device__ __align__(256) float  g_asrc[NN];
__device__ __align__(256) float  g_adst[NN];
__device__ __align__(256) int    g_src[TOTE];
__device__ __align__(256) int    g_dst[TOTE];
__device__ __align__(256) int    g_deg[NN];       // per-dst degree histogram
__device__ __align__(256) int    g_rowptr[NN + 1];
__device__ __align__(256) int    g_pos[NN];       // running fill cursors
__device__ __align__(256) int    g_esrc[TOTE];    // dst-sorted source ids
__device__ __align__(256) float  g_eex[TOTE];     // dst-sorted exp(leaky(alpha))
__device__ __align__(256) int    g_bsum[NBLK];
__device__ __align__(256) int    g_boff[NBLK];
__device__ __align__(256) unsigned char g_mask[NN];
__device__ __align__(256) double g_cs[D];
__device__ __align__(256) double g_cq[D];
__device__ __align__(256) float  g_A[D];
__device__ __align__(256) float  g_B[D];
__device__ __align__(256) float  g_Wa[D * 2 * D]; // combined+scaled final weights (full fp32)
__device__ __align__(256) float  g_Wb[D * 2 * D];
__device__ __align__(256) float  g_ba[D];
__device__ __align__(256) float  g_bb[D];
__device__ __align__(256) int    g_listT[NN];
__device__ __align__(256) int    g_listF[NN];
__device__            int        g_cnt[2];
__device__            int        g_flags[2];

// ---------------- tf32x3 helpers ----------------
__device__ __forceinline__ float tff(float f) {
    unsigned u; asm("cvt.rna.tf32.f32 %0, %1;" : "=r"(u) : "f"(f));
    return __uint_as_float(u);
}
__device__ __forceinline__ void sp3(float f, unsigned& h, unsigned& l) {
    float hf = tff(f);
    h = __float_as_uint(hf);
    l = __float_as_uint(tff(f - hf));
}
__device__ __forceinline__ void mma8(float4& d, const unsigned a[4], unsigned b0, unsigned b1) {
    asm volatile("mma.sync.aligned.m16n8k8.row.col.f32.tf32.tf32.f32 "
                 "{%0,%1,%2,%3},{%4,%5,%6,%7},{%8,%9},{%0,%1,%2,%3};"
                 : "+f"(d.x), "+f"(d.y), "+f"(d.z), "+f"(d.w)
                 : "r"(a[0]), "r"(a[1]), "r"(a[2]), "r"(a[3]), "r"(b0), "r"(b1));
}
// D += A*B with tf32x3 compensation (drops lo*lo term, ~2e-7 rel)
__device__ __forceinline__ void mma3(float4& d, const unsigned ah[4], const unsigned al[4],
                                     unsigned bh0, unsigned bh1, unsigned bl0, unsigned bl1) {
    mma8(d, al, bh0, bh1);
    mma8(d, ah, bl0, bl1);
    mma8(d, ah, bh0, bh1);
}

// ---------------- dtype detection ----------------
__global__ void k_detect(const void* ei, const void* mask) {
    if (threadIdx.x != 0 || blockIdx.x != 0) return;
    const int* e32 = (const int*)ei;
    int allz = 1;
    for (int i = 1; i < 128; i += 2) if (e32[i] != 0) { allz = 0; break; }
    g_flags[0] = allz;
    const unsigned int* m32 = (const unsigned int*)mask;
    int int_like = 1, float_like = 1;
    for (int i = 0; i < 256; i++) {
        unsigned int w = m32[i];
        if (!(w == 0u || w == 1u)) int_like = 0;
        if (!(w == 0u || w == 0x3F800000u)) float_like = 0;
    }
    g_flags[1] = int_like ? 1 : (float_like ? 2 : 0);
}

// ---------------- zero counters ----------------
__global__ __launch_bounds__(256) void k_zero() {
    int i = blockIdx.x * 256 + threadIdx.x;
    if (i < NN) g_deg[i] = 0;
    if (i < D) { g_cs[i] = 0.0; g_cq[i] = 0.0; }
    if (i == 0) { g_cnt[0] = 0; g_cnt[1] = 0; }
}

// ---------------- normalize inputs + degree histogram ----------------
__global__ __launch_bounds__(256) void k_convert(const void* ei, const void* maskp) {
    int i = blockIdx.x * 256 + threadIdx.x;
    int e64 = g_flags[0], mk = g_flags[1];
    if (i < TOTE) {
        int s, d;
        if (i < EE) {
            if (e64) {
                const long long* e = (const long long*)ei;
                s = (int)e[i]; d = (int)e[EE + i];
            } else {
                const int* e = (const int*)ei;
                s = e[i]; d = e[EE + i];
            }
        } else { s = d = i - EE; }
        g_src[i] = s; g_dst[i] = d;
        if ((unsigned)s < NN && (unsigned)d < NN) atomicAdd(&g_deg[d], 1);
    }
    if (i < NN) {
        unsigned char m;
        if (mk == 0)      m = ((const unsigned char*)maskp)[i] != 0;
        else if (mk == 1) m = ((const int*)maskp)[i] != 0;
        else              m = ((const float*)maskp)[i] != 0.f;
        g_mask[i] = m;
    }
}

// ---------------- two-level exclusive scan over degrees ----------------
__global__ __launch_bounds__(1024) void k_scan1() {
    __shared__ int sh[1024];
    int b = blockIdx.x, t = threadIdx.x;
    int i = b * 1024 + t;
    sh[t] = (i < NN) ? g_deg[i] : 0;
    __syncthreads();
    for (int off = 512; off > 0; off >>= 1) {
        if (t < off) sh[t] += sh[t + off];
        __syncthreads();
    }
    if (t == 0) g_bsum[b] = sh[0];
}
__global__ void k_scan2() {
    if (threadIdx.x != 0) return;
    int run = 0;
    for (int b = 0; b < NBLK; b++) { g_boff[b] = run; run += g_bsum[b]; }
    g_rowptr[NN] = run;
}
__global__ __launch_bounds__(1024) void k_scan3() {
    __shared__ int sh[1024];
    int b = blockIdx.x, t = threadIdx.x;
    int i = b * 1024 + t;
    int v = (i < NN) ? g_deg[i] : 0;
    sh[t] = v;
    __syncthreads();
    int acc = v;
    for (int off = 1; off < 1024; off <<= 1) {
        int add = (t >= off) ? sh[t - off] : 0;
        __syncthreads();
        acc += add;
        sh[t] = acc;
        __syncthreads();
    }
    if (i < NN) {
        int ex = acc - v + g_boff[b];   // exclusive prefix
        g_rowptr[i] = ex;
        g_pos[i] = ex;
    }
}

// ---------------- mask compaction ----------------
__global__ __launch_bounds__(256) void k_compact() {
    int i = blockIdx.x * blockDim.x + threadIdx.x;
    if (i < NN) {
        if (g_mask[i]) g_listT[atomicAdd(&g_cnt[0], 1)] = i;
        else           g_listF[atomicAdd(&g_cnt[1], 1)] = i;
    }
}

// ---------------- fused transform+GAT with tf32x3 tensor cores ----------------
// Stage 1: xmix = mix(relu(x@W1^T+b1), relu(x@W0^T+b0), mask) -> sX (fp32)
// Stage 2: xp = xmix@GW^T -> g_xp ; a_src/a_dst dots -> g_asrc/g_adst
__global__ __launch_bounds__(256) void k_tg(
    const float* __restrict__ x,
    const float* __restrict__ W0, const float* __restrict__ b0v,
    const float* __restrict__ W1, const float* __restrict__ b1v,
    const float* __restrict__ GW,
    const float* __restrict__ att_s, const float* __restrict__ att_d)
{
    __shared__ __align__(16) float sX[64 * 132];  // fp32 mixed-feature tile
    __shared__ __align__(16) float sA[64 * 12];
    __shared__ __align__(16) float sB0[128 * 8];
    __shared__ __align__(16) float sB1[128 * 8];
    __shared__ float sPS[64], sPD[64];
    __shared__ unsigned char sM[64];

    int tid = threadIdx.x, lane = tid & 31, warp = tid >> 5;
    int wm = warp >> 2, wn = warp & 3;
    int g = lane >> 2, t = lane & 3;
    int base = blockIdx.x * 64;

    if (tid < 64) {
        sPS[tid] = 0.f; sPD[tid] = 0.f;
        int gr = base + tid;
        sM[tid] = (gr < NN) ? g_mask[gr] : (unsigned char)0;
    }

    float4 acc0[2][4], acc1[2][4];
#pragma unroll
    for (int mt = 0; mt < 2; mt++)
#pragma unroll
        for (int nt = 0; nt < 4; nt++) {
            acc0[mt][nt] = make_float4(0.f, 0.f, 0.f, 0.f);
            acc1[mt][nt] = make_float4(0.f, 0.f, 0.f, 0.f);
        }

    // ---- stage 1: dual tf32x3 GEMM over K=128 ----
    for (int kc = 0; kc < 16; kc++) {
        if (tid < 128) {
            int row = tid >> 1, seg = tid & 1, grow = base + row;
            float4 av = make_float4(0.f, 0.f, 0.f, 0.f);
            if (grow < NN) av = *(const float4*)&x[(size_t)grow * D + kc * 8 + seg * 4];
            *(float4*)&sA[row * 12 + seg * 4] = av;
        }
        {
            int j = tid >> 1, seg = tid & 1;
            *(float4*)&sB0[j * 8 + seg * 4] = *(const float4*)&W0[j * D + kc * 8 + seg * 4];
            *(float4*)&sB1[j * 8 + seg * 4] = *(const float4*)&W1[j * D + kc * 8 + seg * 4];
        }
        __syncthreads();
        unsigned ah[2][4], al[2][4];
#pragma unroll
        for (int mt = 0; mt < 2; mt++) {
            int r = wm * 32 + mt * 16 + g;
            sp3(sA[r * 12 + t],           ah[mt][0], al[mt][0]);
            sp3(sA[(r + 8) * 12 + t],     ah[mt][1], al[mt][1]);
            sp3(sA[r * 12 + t + 4],       ah[mt][2], al[mt][2]);
            sp3(sA[(r + 8) * 12 + t + 4], ah[mt][3], al[mt][3]);
        }
#pragma unroll
        for (int nt = 0; nt < 4; nt++) {
            int n = wn * 32 + nt * 8 + g;
            unsigned bh0, bl0, bh1, bl1;
            sp3(sB0[n * 8 + t],     bh0, bl0);
            sp3(sB0[n * 8 + t + 4], bh1, bl1);
            mma3(acc0[0][nt], ah[0], al[0], bh0, bh1, bl0, bl1);
            mma3(acc0[1][nt], ah[1], al[1], bh0, bh1, bl0, bl1);
            sp3(sB1[n * 8 + t],     bh0, bl0);
            sp3(sB1[n * 8 + t + 4], bh1, bl1);
            mma3(acc1[0][nt], ah[0], al[0], bh0, bh1, bl0, bl1);
            mma3(acc1[1][nt], ah[1], al[1], bh0, bh1, bl0, bl1);
        }
        __syncthreads();
    }

    // ---- stage-1 epilogue: bias + relu + mix -> sX (fp32) ----
#pragma unroll
    for (int nt = 0; nt < 4; nt++) {
        int cn = wn * 32 + nt * 8 + t * 2;
        float b0x = b0v[cn], b0y = b0v[cn + 1];
        float b1x = b1v[cn], b1y = b1v[cn + 1];
#pragma unroll
        for (int mt = 0; mt < 2; mt++) {
            int r0 = wm * 32 + mt * 16 + g;
            bool m0 = sM[r0] != 0, m1 = sM[r0 + 8] != 0;
            float4 u0 = acc0[mt][nt], u1 = acc1[mt][nt];
            float v0, v1, ra, rb;
            v0 = fmaxf(u0.x + b0x, 0.f); v1 = fmaxf(u1.x + b1x, 0.f);
            ra = m0 ? (ZA * v1 + ZB * v0) : (ZA * v0 + ZB * v1);
            v0 = fmaxf(u0.y + b0y, 0.f); v1 = fmaxf(u1.y + b1y, 0.f);
            rb = m0 ? (ZA * v1 + ZB * v0) : (ZA * v0 + ZB * v1);
            *(float2*)&sX[r0 * 132 + cn] = make_float2(ra, rb);
            v0 = fmaxf(u0.z + b0x, 0.f); v1 = fmaxf(u1.z + b1x, 0.f);
            ra = m1 ? (ZA * v1 + ZB * v0) : (ZA * v0 + ZB * v1);
            v0 = fmaxf(u0.w + b0y, 0.f); v1 = fmaxf(u1.w + b1y, 0.f);
            rb = m1 ? (ZA * v1 + ZB * v0) : (ZA * v0 + ZB * v1);
            *(float2*)&sX[(r0 + 8) * 132 + cn] = make_float2(ra, rb);
        }
    }
    __syncthreads();

    // ---- stage 2: xp = sX @ GW^T (tf32x3) ----
#pragma unroll
    for (int mt = 0; mt < 2; mt++)
#pragma unroll
        for (int nt = 0; nt < 4; nt++)
            acc0[mt][nt] = make_float4(0.f, 0.f, 0.f, 0.f);

    for (int kc = 0; kc < 16; kc++) {
        {
            int j = tid >> 1, seg = tid & 1;
            *(float4*)&sB0[j * 8 + seg * 4] = *(const float4*)&GW[j * D + kc * 8 + seg * 4];
        }
        __syncthreads();
        unsigned ah[2][4], al[2][4];
#pragma unroll
        for (int mt = 0; mt < 2; mt++) {
            int r = wm * 32 + mt * 16 + g;
            sp3(sX[r * 132 + kc * 8 + t],           ah[mt][0], al[mt][0]);
            sp3(sX[(r + 8) * 132 + kc * 8 + t],     ah[mt][1], al[mt][1]);
            sp3(sX[r * 132 + kc * 8 + t + 4],       ah[mt][2], al[mt][2]);
            sp3(sX[(r + 8) * 132 + kc * 8 + t + 4], ah[mt][3], al[mt][3]);
        }
#pragma unroll
        for (int nt = 0; nt < 4; nt++) {
            int n = wn * 32 + nt * 8 + g;
            unsigned bh0, bl0, bh1, bl1;
            sp3(sB0[n * 8 + t],     bh0, bl0);
            sp3(sB0[n * 8 + t + 4], bh1, bl1);
            mma3(acc0[0][nt], ah[0], al[0], bh0, bh1, bl0, bl1);
            mma3(acc0[1][nt], ah[1], al[1], bh0, bh1, bl0, bl1);
        }
        __syncthreads();
    }

    // ---- stage-2 epilogue: write xp, reduce attention dots ----
    float asx[4][2], adx[4][2];
#pragma unroll
    for (int nt = 0; nt < 4; nt++) {
        int cn = wn * 32 + nt * 8 + t * 2;
        asx[nt][0] = att_s[cn]; asx[nt][1] = att_s[cn + 1];
        adx[nt][0] = att_d[cn]; adx[nt][1] = att_d[cn + 1];
    }
#pragma unroll
    for (int mt = 0; mt < 2; mt++) {
        float p0 = 0.f, p1 = 0.f, q0 = 0.f, q1 = 0.f;
#pragma unroll
        for (int nt = 0; nt < 4; nt++) {
            float4 u = acc0[mt][nt];
            p0 += u.x * asx[nt][0] + u.y * asx[nt][1];
            q0 += u.x * adx[nt][0] + u.y * adx[nt][1];
            p1 += u.z * asx[nt][0] + u.w * asx[nt][1];
            q1 += u.z * adx[nt][0] + u.w * adx[nt][1];
        }
        p0 += __shfl_xor_sync(0xFFFFFFFFu, p0, 1); p0 += __shfl_xor_sync(0xFFFFFFFFu, p0, 2);
        q0 += __shfl_xor_sync(0xFFFFFFFFu, q0, 1); q0 += __shfl_xor_sync(0xFFFFFFFFu, q0, 2);
        p1 += __shfl_xor_sync(0xFFFFFFFFu, p1, 1); p1 += __shfl_xor_sync(0xFFFFFFFFu, p1, 2);
        q1 += __shfl_xor_sync(0xFFFFFFFFu, q1, 1); q1 += __shfl_xor_sync(0xFFFFFFFFu, q1, 2);
        if (t == 0) {
            int r0 = wm * 32 + mt * 16 + g;
            atomicAdd(&sPS[r0], p0);     atomicAdd(&sPD[r0], q0);
            atomicAdd(&sPS[r0 + 8], p1); atomicAdd(&sPD[r0 + 8], q1);
        }
    }
#pragma unroll
    for (int mt = 0; mt < 2; mt++)
#pragma unroll
        for (int nt = 0; nt < 4; nt++) {
            int r0 = base + wm * 32 + mt * 16 + g;
            int cn = wn * 32 + nt * 8 + t * 2;
            float4 u = acc0[mt][nt];
            if (r0 < NN)     *(float2*)&g_xp[(size_t)r0 * D + cn]       = make_float2(u.x, u.y);
            if (r0 + 8 < NN) *(float2*)&g_xp[(size_t)(r0 + 8) * D + cn] = make_float2(u.z, u.w);
        }
    __syncthreads();
    if (tid < 64) {
        int gr = base + tid;
        if (gr < NN) { g_asrc[gr] = sPS[tid]; g_adst[gr] = sPD[tid]; }
    }
}

// ---------------- fill dst-sorted edge lists + per-edge exp weights ----------------
__global__ __launch_bounds__(256) void k_fill() {
    int e = blockIdx.x * 256 + threadIdx.x;
    if (e >= TOTE) return;
    int s = g_src[e], d = g_dst[e];
    if ((unsigned)s >= NN || (unsigned)d >= NN) return;
    float al = g_asrc[s] + g_adst[d];
    al = al > 0.f ? al : NEG * al;
    float ex = expf(al);
    int p = atomicAdd(&g_pos[d], 1);
    g_esrc[p] = s;
    g_eex[p] = ex;
}

// ---------------- gather-aggregate: one warp per dst, normalized store ----------------
__global__ __launch_bounds__(256) void k_agg() {
    int wg = (blockIdx.x * 256 + threadIdx.x) >> 5;
    int lane = threadIdx.x & 31;
    if (wg >= NN) return;
    int beg = g_rowptr[wg], end = g_rowptr[wg + 1];
    float4 acc = make_float4(0.f, 0.f, 0.f, 0.f);
    float den = 0.f;
    for (int b = beg; b < end; b += 32) {
        int myi = b + lane;
        int sl = 0; float exl = 0.f;
        if (myi < end) { sl = __ldg(&g_esrc[myi]); exl = __ldg(&g_eex[myi]); }
        int m = min(32, end - b);
        for (int j = 0; j < m; j++) {
            int s = __shfl_sync(0xFFFFFFFFu, sl, j);
            float ex = __shfl_sync(0xFFFFFFFFu, exl, j);
            float4 v = *(const float4*)&g_xp[(size_t)s * D + lane * 4];
            acc.x = fmaf(v.x, ex, acc.x);
            acc.y = fmaf(v.y, ex, acc.y);
            acc.z = fmaf(v.z, ex, acc.z);
            acc.w = fmaf(v.w, ex, acc.w);
            den += ex;
        }
    }
    float inv = 1.f / (den + 1e-16f);
    *(float4*)&g_acc[(size_t)wg * D + lane * 4] =
        make_float4(acc.x * inv, acc.y * inv, acc.z * inv, acc.w * inv);
}

// ---------------- GraphNorm stats over out = g_acc + gat_bias ----------------
__global__ __launch_bounds__(128) void k_colstats(const float* __restrict__ gb) {
    int c = threadIdx.x;
    float b = gb[c];
    double s = 0.0, q = 0.0;
    for (int r = blockIdx.x; r < NN; r += gridDim.x) {
        float o = g_acc[(size_t)r * D + c] + b;
        s += o; q += (double)o * o;
    }
    atomicAdd(&g_cs[c], s);
    atomicAdd(&g_cq[c], q);
}

// ---------------- GraphNorm coefficients: norm(o) = o*A + B ----------------
__global__ void k_finalize(const float* __restrict__ gnw, const float* __restrict__ gnb,
                           const float* __restrict__ gms, const float* __restrict__ gatb) {
    int c = threadIdx.x;
    double m  = g_cs[c] / (double)NN;
    double e2 = g_cq[c] / (double)NN;
    double s  = (double)gms[c];
    double var = e2 - 2.0 * s * m * m + s * s * m * m;
    double A = (double)gnw[c] / sqrt(var + 1e-5);
    double B = (double)gnb[c] - s * m * A;
    g_A[c] = (float)A;
    g_B[c] = (float)((double)gatb[c] * A + B);
}

// ---------------- precompute mixed + norm-scaled final weights (full fp32) ----------------
__global__ __launch_bounds__(256) void k_prep(const float* __restrict__ Wc0, const float* __restrict__ bc0,
                                              const float* __restrict__ Wc1, const float* __restrict__ bc1) {
    __shared__ float2 rr[256];
    int j = blockIdx.x, c = threadIdx.x;
    float w0 = Wc0[j * 256 + c], w1 = Wc1[j * 256 + c];
    float wa = ZA * w1 + ZB * w0;
    float wb = ZA * w0 + ZB * w1;
    float pa = 0.f, pb = 0.f;
    if (c < D) {
        float Bv = g_B[c], A = g_A[c];
        pa = wa * Bv; pb = wb * Bv;
        wa *= A; wb *= A;
    }
    g_Wa[j * 256 + c] = wa;
    g_Wb[j * 256 + c] = wb;
    rr[c] = make_float2(pa, pb);
    __syncthreads();
    for (int off = 128; off > 0; off >>= 1) {
        if (c < off) { rr[c].x += rr[c + off].x; rr[c].y += rr[c + off].y; }
        __syncthreads();
    }
    if (c == 0) {
        g_ba[j] = ZA * bc1[j] + ZB * bc0[j] + rr[0].x;
        g_bb[j] = ZA * bc0[j] + ZB * bc1[j] + rr[0].y;
    }
}

// ---------------- final GEMM (tf32x3) over compacted node lists ----------------
template <int WHICH>
__global__ __launch_bounds__(256) void k_final(const float* __restrict__ x_, float* __restrict__ out) {
    __shared__ __align__(16) float sA[64 * 12];
    __shared__ __align__(16) float sB[128 * 8];
    __shared__ int sIdx[64];
    int cnt = g_cnt[WHICH];
    int base = blockIdx.x * 64;
    if (base >= cnt) return;
    const int*   list = (WHICH == 0) ? g_listT : g_listF;
    const float* W    = (WHICH == 0) ? g_Wa : g_Wb;
    const float* bias = (WHICH == 0) ? g_ba : g_bb;
    int tid = threadIdx.x, lane = tid & 31, warp = tid >> 5;
    int wm = warp >> 2, wn = warp & 3;
    int g = lane >> 2, t = lane & 3;
    if (tid < 64) sIdx[tid] = (base + tid < cnt) ? list[base + tid] : -1;
    __syncthreads();

    float4 acc[2][4];
#pragma unroll
    for (int mt = 0; mt < 2; mt++)
#pragma unroll
        for (int nt = 0; nt < 4; nt++) acc[mt][nt] = make_float4(0.f, 0.f, 0.f, 0.f);

    for (int kc = 0; kc < 32; kc++) {
        if (tid < 128) {
            int row = tid >> 1, seg = tid & 1;
            int aidx = sIdx[row];
            int k0 = kc * 8 + seg * 4;
            float4 av = make_float4(0.f, 0.f, 0.f, 0.f);
            if (aidx >= 0) {
                if (k0 < D) av = *(const float4*)&g_acc[(size_t)aidx * D + k0];
                else        av = *(const float4*)&x_[(size_t)aidx * D + (k0 - D)];
            }
            *(float4*)&sA[row * 12 + seg * 4] = av;
        }
        {
            int j = tid >> 1, seg = tid & 1;
            *(float4*)&sB[j * 8 + seg * 4] = *(const float4*)&W[j * 256 + kc * 8 + seg * 4];
        }
        __syncthreads();
        unsigned ah[2][4], al[2][4];
#pragma unroll
        for (int mt = 0; mt < 2; mt++) {
            int r = wm * 32 + mt * 16 + g;
            sp3(sA[r * 12 + t],           ah[mt][0], al[mt][0]);
            sp3(sA[(r + 8) * 12 + t],     ah[mt][1], al[mt][1]);
            sp3(sA[r * 12 + t + 4],       ah[mt][2], al[mt][2]);
            sp3(sA[(r + 8) * 12 + t + 4], ah[mt][3], al[mt][3]);
        }
#pragma unroll
        for (int nt = 0; nt < 4; nt++) {
            int n = wn * 32 + nt * 8 + g;
            unsigned bh0, bl0, bh1, bl1;
            sp3(sB[n * 8 + t],     bh0, bl0);
            sp3(sB[n * 8 + t + 4], bh1, bl1);
            mma3(acc[0][nt], ah[0], al[0], bh0, bh1, bl0, bl1);
            mma3(acc[1][nt], ah[1], al[1], bh0, bh1, bl0, bl1);
        }
        __syncthreads();
    }
#pragma unroll
    for (int nt = 0; nt < 4; nt++) {
        int cn = wn * 32 + nt * 8 + t * 2;
        float bx = bias[cn], by = bias[cn + 1];
#pragma unroll
        for (int mt = 0; mt < 2; mt++) {
            int r = wm * 32 + mt * 16 + g;
            int i0 = sIdx[r], i1 = sIdx[r + 8];
            float4 u = acc[mt][nt];
            if (i0 >= 0) *(float2*)&out[(size_t)i0 * D + cn] = make_float2(u.x + bx, u.y + by);
            if (i1 >= 0) *(float2*)&out[(size_t)i1 * D + cn] = make_float2(u.z + bx, u.w + by);
        }
    }
}

// ---------------- launch ----------------
extern "C" void kernel_launch(void* const* d_in, const int* in_sizes, int n_in,
                              void* d_out, int out_size) {
    const float* x_      = (const float*)d_in[0];
    const float* W_t0    = (const float*)d_in[2];
    const float* b_t0    = (const float*)d_in[3];
    const float* W_t1    = (const float*)d_in[4];
    const float* b_t1    = (const float*)d_in[5];
    const float* gat_W   = (const float*)d_in[6];
    const float* att_src = (const float*)d_in[7];
    const float* att_dst = (const float*)d_in[8];
    const float* gat_b   = (const float*)d_in[9];
    const float* gn_w    = (const float*)d_in[10];
    const float* gn_b    = (const float*)d_in[11];
    const float* gn_ms   = (const float*)d_in[12];
    const float* W_c0    = (const float*)d_in[13];
    const float* b_c0    = (const float*)d_in[14];
    const float* W_c1    = (const float*)d_in[15];
    const float* b_c1    = (const float*)d_in[16];
    const void*  ei      = d_in[17];
    const void*  mask    = d_in[18];
    float* out = (float*)d_out;

    int gb = (NN + 63) / 64;

    k_detect<<<1, 32>>>(ei, mask);
    k_zero<<<(NN + 255) / 256, 256>>>();
    k_convert<<<(TOTE + 255) / 256, 256>>>(ei, mask);
    k_scan1<<<NBLK, 1024>>>();
    k_scan2<<<1, 32>>>();
    k_scan3<<<NBLK, 1024>>>();
    k_compact<<<(NN + 255) / 256, 256>>>();
    k_tg<<<gb, 256>>>(x_, W_t0, b_t0, W_t1, b_t1, gat_W, att_src, att_dst);
    k_fill<<<(TOTE + 255) / 256, 256>>>();
    k_agg<<<(NN * 32 + 255) / 256, 256>>>();
    k_colstats<<<512, 128>>>(gat_b);
    k_finalize<<<1, 128>>>(gn_w, gn_b, gn_ms, gat_b);
    k_prep<<<128, 256>>>(W_c0, b_c0, W_c1, b_c1);
    k_final<0><<<gb, 256>>>(x_, out);
    k_final<1><<<gb, 256>>>(x_, out);
}